// round 6
// baseline (speedup 1.0000x reference)
#include <cuda_runtime.h>
#include <cuda_fp16.h>
#include <cstdint>
#include <math.h>

#define N_NODES 50000
#define N_EDGES 800000
#define FDIM    128
#define SCAN_B  ((N_NODES + 1023) / 1024)

// ---------------- static device scratch ----------------
__device__ int    g_deg[N_NODES];
__device__ int    g_cnt[N_NODES];
__device__ int    g_ofs[N_NODES];
__device__ int    g_rp[N_NODES + 1];
__device__ float  g_dinv[N_NODES];
__device__ int    g_col[N_EDGES];
__device__ float  g_wt[N_EDGES];
__device__ int    g_bsum[SCAN_B];
__device__ int    g_bofs[SCAN_B];
__device__ float  g_T1[N_NODES * FDIM];
__device__ float  g_T2[N_NODES * FDIM];
__device__ float  g_T3[N_NODES * FDIM];
__device__ float  g_T4[N_NODES * FDIM];
__device__ float  g_H [N_NODES * FDIM];
__device__ float  g_H2[N_NODES * FDIM];
__device__ __half g_Xh [N_NODES * FDIM];
__device__ __half g_T1h[N_NODES * FDIM];
__device__ __half g_T2h[N_NODES * FDIM];
__device__ __half g_T3h[N_NODES * FDIM];
__device__ __half g_Hh [N_NODES * FDIM];
__device__ __half g_H2h[N_NODES * FDIM];
__device__ float  g_C2[5 * FDIM];
__device__ float  g_c0[1];

// ---------------- f32x2 packed helpers ----------------
typedef unsigned long long ull;
__device__ __forceinline__ ull pk2(float x, float y) {
    ull r; asm("mov.b64 %0,{%1,%2};" : "=l"(r) : "f"(x), "f"(y)); return r;
}
__device__ __forceinline__ void upk2(ull v, float& x, float& y) {
    asm("mov.b64 {%0,%1},%2;" : "=f"(x), "=f"(y) : "l"(v));
}
__device__ __forceinline__ void fma2(ull& d, ull a, ull b) {
    asm("fma.rn.f32x2 %0,%1,%2,%0;" : "+l"(d) : "l"(a), "l"(b));
}

// ---------------- preprocessing ----------------
__global__ void k_zero() {
    int i = blockIdx.x * blockDim.x + threadIdx.x;
    if (i < N_NODES) { g_deg[i] = 0; g_cnt[i] = 0; }
}

__global__ void k_count(const int* __restrict__ ei) {
    int e = blockIdx.x * blockDim.x + threadIdx.x;
    if (e < N_EDGES) {
        int s = ei[e], d = ei[N_EDGES + e];
        if (s != d) {
            atomicAdd(&g_deg[s], 1);
            atomicAdd(&g_cnt[d], 1);
        }
    }
}

__global__ void k_dinv() {
    int i = blockIdx.x * blockDim.x + threadIdx.x;
    if (i < N_NODES) {
        int dg = g_deg[i];
        g_dinv[i] = (dg > 0) ? rsqrtf((float)dg) : 0.0f;
    }
}

__global__ void k_scanA() {
    __shared__ int wsum[32];
    int tid  = threadIdx.x;
    int lane = tid & 31, wid = tid >> 5;
    int i = blockIdx.x * 1024 + tid;
    int v = (i < N_NODES) ? g_cnt[i] : 0;
    int x = v;
    #pragma unroll
    for (int off = 1; off < 32; off <<= 1) {
        int y = __shfl_up_sync(0xFFFFFFFFu, x, off);
        if (lane >= off) x += y;
    }
    if (lane == 31) wsum[wid] = x;
    __syncthreads();
    if (wid == 0) {
        int y = wsum[lane];
        #pragma unroll
        for (int off = 1; off < 32; off <<= 1) {
            int z = __shfl_up_sync(0xFFFFFFFFu, y, off);
            if (lane >= off) y += z;
        }
        wsum[lane] = y;
    }
    __syncthreads();
    int excl = x - v + (wid > 0 ? wsum[wid - 1] : 0);
    if (i < N_NODES) g_rp[i] = excl;
    if (tid == 0) g_bsum[blockIdx.x] = wsum[31];
}

__global__ void k_scanB() {
    int run = 0;
    for (int b = 0; b < SCAN_B; ++b) {
        g_bofs[b] = run;
        run += g_bsum[b];
    }
    g_rp[N_NODES] = run;
}

__global__ void k_scanC() {
    int i = blockIdx.x * 1024 + threadIdx.x;
    if (i < N_NODES) {
        int r = g_rp[i] + g_bofs[blockIdx.x];
        g_rp[i]  = r;
        g_ofs[i] = r;
    }
}

__global__ void k_fill(const int* __restrict__ ei) {
    int e = blockIdx.x * blockDim.x + threadIdx.x;
    if (e < N_EDGES) {
        int s = ei[e], d = ei[N_EDGES + e];
        if (s != d) {
            int p = atomicAdd(&g_ofs[d], 1);
            g_col[p] = s;
            g_wt[p]  = -g_dinv[s] * g_dinv[d];
        }
    }
}

__global__ void k_fold(const float* __restrict__ W2, const float* __restrict__ b2,
                       const float* __restrict__ Wl, const float* __restrict__ bl) {
    int k = blockIdx.x;
    int f = threadIdx.x;
    const float* row = W2 + ((size_t)k * 128 + f) * 128;
    float s = 0.f;
    #pragma unroll 4
    for (int w = 0; w < 128; ++w) s += row[w] * Wl[w];
    g_C2[k * 128 + f] = s;
    if (k == 0 && f == 0) {
        float c = bl[0];
        for (int w = 0; w < 128; ++w) c += b2[w] * Wl[w];
        g_c0[0] = c;
    }
}

// fp32 -> fp16 shadow conversion (for x)
__global__ void k_h16(const float* __restrict__ src, __half* __restrict__ dst) {
    int i = blockIdx.x * blockDim.x + threadIdx.x;   // one float4 per thread
    if (i < N_NODES * 32) {
        float4 v = ((const float4*)src)[i];
        __half2 a = __floats2half2_rn(v.x, v.y);
        __half2 b = __floats2half2_rn(v.z, v.w);
        uint2 u;
        u.x = *reinterpret_cast<uint32_t*>(&a);
        u.y = *reinterpret_cast<uint32_t*>(&b);
        ((uint2*)dst)[i] = u;
    }
}

// ---------------- SpMV: fp16 gather, fp32 accumulate ----------------
// out = (cheb ? 2*L*vin - prev : L*vin); writes fp32 + fp16 shadow
__global__ void k_spmv(const __half* __restrict__ vinH,
                       const float* __restrict__ prev,
                       float* __restrict__ vout, __half* __restrict__ voutH,
                       int cheb) {
    int w    = (blockIdx.x * blockDim.x + threadIdx.x) >> 5;
    int lane = threadIdx.x & 31;
    if (w >= N_NODES) return;
    int beg = g_rp[w], end = g_rp[w + 1];

    float ax = 0.f, ay = 0.f, az = 0.f, aw = 0.f;
    int j = beg;
    for (; j + 1 < end; j += 2) {
        int   s0 = g_col[j],     s1 = g_col[j + 1];
        float w0 = g_wt[j],      w1 = g_wt[j + 1];
        uint2 u0 = ((const uint2*)(vinH + (size_t)s0 * 128))[lane];
        uint2 u1 = ((const uint2*)(vinH + (size_t)s1 * 128))[lane];
        float2 f00 = __half22float2(*reinterpret_cast<__half2*>(&u0.x));
        float2 f01 = __half22float2(*reinterpret_cast<__half2*>(&u0.y));
        float2 f10 = __half22float2(*reinterpret_cast<__half2*>(&u1.x));
        float2 f11 = __half22float2(*reinterpret_cast<__half2*>(&u1.y));
        ax += w0 * f00.x + w1 * f10.x;
        ay += w0 * f00.y + w1 * f10.y;
        az += w0 * f01.x + w1 * f11.x;
        aw += w0 * f01.y + w1 * f11.y;
    }
    if (j < end) {
        int   s0 = g_col[j];
        float w0 = g_wt[j];
        uint2 u0 = ((const uint2*)(vinH + (size_t)s0 * 128))[lane];
        float2 f00 = __half22float2(*reinterpret_cast<__half2*>(&u0.x));
        float2 f01 = __half22float2(*reinterpret_cast<__half2*>(&u0.y));
        ax += w0 * f00.x; ay += w0 * f00.y; az += w0 * f01.x; aw += w0 * f01.y;
    }
    float4 r;
    if (cheb) {
        float4 p = ((const float4*)prev)[w * 32 + lane];
        r.x = 2.0f * ax - p.x;
        r.y = 2.0f * ay - p.y;
        r.z = 2.0f * az - p.z;
        r.w = 2.0f * aw - p.w;
    } else {
        r.x = ax; r.y = ay; r.z = az; r.w = aw;
    }
    ((float4*)vout)[w * 32 + lane] = r;
    __half2 h0 = __floats2half2_rn(r.x, r.y);
    __half2 h1 = __floats2half2_rn(r.z, r.w);
    uint2 hu;
    hu.x = *reinterpret_cast<uint32_t*>(&h0);
    hu.y = *reinterpret_cast<uint32_t*>(&h1);
    ((uint2*)voutH)[w * 32 + lane] = hu;
}

// ---------------- fused 5-slice GEMM, f32x2, pre-packed B ----------------
struct A5 { const float* p[5]; };

template <bool RELU>
__global__ __launch_bounds__(256, 2)
void k_gemm(A5 A, const float* __restrict__ B,
            const float* __restrict__ bias, float* __restrict__ C,
            __half* __restrict__ Ch) {
    __shared__ float As[16][132];        // [k][m], padded
    __shared__ __align__(16) ull Bs2[16][128];  // [k][n] duplicated (b,b) pairs

    const int tid = threadIdx.x;
    const int tx  = tid & 15;   // n-tile index (8 cols)
    const int ty  = tid >> 4;   // m-tile index (8 rows)
    const int m0  = blockIdx.x * 128;

    ull accp[4][8];   // [m-pair][n]
    #pragma unroll
    for (int ii = 0; ii < 4; ++ii)
        #pragma unroll
        for (int j = 0; j < 8; ++j) accp[ii][j] = 0ull;

    for (int k = 0; k < 5; ++k) {
        const float* Ak = A.p[k];
        const float* Bk = B + k * 128 * 128;
        for (int kt = 0; kt < 128; kt += 16) {
            // A tile: 128 rows x 16 k -> transposed As[k][m]
            #pragma unroll
            for (int i = 0; i < 2; ++i) {
                int f = tid + i * 256;
                int row = f >> 2, cv = f & 3;
                int gm = m0 + row;
                float4 v = make_float4(0.f, 0.f, 0.f, 0.f);
                if (gm < N_NODES)
                    v = *(const float4*)(Ak + (size_t)gm * 128 + kt + cv * 4);
                As[cv * 4 + 0][row] = v.x;
                As[cv * 4 + 1][row] = v.y;
                As[cv * 4 + 2][row] = v.z;
                As[cv * 4 + 3][row] = v.w;
            }
            // B tile: 16 x 128, stored as duplicated (b,b) ull pairs
            #pragma unroll
            for (int i = 0; i < 2; ++i) {
                int f = tid + i * 256;
                int br = f >> 5, bc = f & 31;
                float4 v = *(const float4*)(Bk + (kt + br) * 128 + bc * 4);
                Bs2[br][bc * 4 + 0] = pk2(v.x, v.x);
                Bs2[br][bc * 4 + 1] = pk2(v.y, v.y);
                Bs2[br][bc * 4 + 2] = pk2(v.z, v.z);
                Bs2[br][bc * 4 + 3] = pk2(v.w, v.w);
            }
            __syncthreads();
            #pragma unroll
            for (int kk = 0; kk < 16; ++kk) {
                ulonglong2 a01 = *(const ulonglong2*)&As[kk][ty * 8];
                ulonglong2 a23 = *(const ulonglong2*)&As[kk][ty * 8 + 4];
                ull ap[4] = { a01.x, a01.y, a23.x, a23.y };
                ull bb[8];
                #pragma unroll
                for (int q = 0; q < 4; ++q) {
                    ulonglong2 bp = *(const ulonglong2*)&Bs2[kk][tx * 8 + q * 2];
                    bb[q * 2 + 0] = bp.x;
                    bb[q * 2 + 1] = bp.y;
                }
                #pragma unroll
                for (int ii = 0; ii < 4; ++ii)
                    #pragma unroll
                    for (int j = 0; j < 8; ++j)
                        fma2(accp[ii][j], ap[ii], bb[j]);
            }
            __syncthreads();
        }
    }
    // epilogue: unpack, bias (+relu), store fp32 + fp16 shadow
    #pragma unroll
    for (int ii = 0; ii < 4; ++ii) {
        float r0[8], r1[8];
        #pragma unroll
        for (int j = 0; j < 8; ++j) upk2(accp[ii][j], r0[j], r1[j]);
        #pragma unroll
        for (int h = 0; h < 2; ++h) {
            float* rr = h ? r1 : r0;
            int gm = m0 + ty * 8 + 2 * ii + h;
            if (gm >= N_NODES) continue;
            #pragma unroll
            for (int j = 0; j < 8; j += 4) {
                float4 r;
                r.x = rr[j + 0] + bias[tx * 8 + j + 0];
                r.y = rr[j + 1] + bias[tx * 8 + j + 1];
                r.z = rr[j + 2] + bias[tx * 8 + j + 2];
                r.w = rr[j + 3] + bias[tx * 8 + j + 3];
                if (RELU) {
                    r.x = fmaxf(r.x, 0.f); r.y = fmaxf(r.y, 0.f);
                    r.z = fmaxf(r.z, 0.f); r.w = fmaxf(r.w, 0.f);
                }
                *(float4*)(C + (size_t)gm * 128 + tx * 8 + j) = r;
                __half2 h0 = __floats2half2_rn(r.x, r.y);
                __half2 h1 = __floats2half2_rn(r.z, r.w);
                uint2 hu;
                hu.x = *reinterpret_cast<uint32_t*>(&h0);
                hu.y = *reinterpret_cast<uint32_t*>(&h1);
                *(uint2*)(Ch + (size_t)gm * 128 + tx * 8 + j) = hu;
            }
        }
    }
}

// ---------------- fused layer-2 + head ----------------
__global__ void k_out(A5 T, float* __restrict__ out) {
    __shared__ float c2[5 * 128];
    for (int i = threadIdx.x; i < 5 * 128; i += blockDim.x) c2[i] = g_C2[i];
    __syncthreads();
    int row  = blockIdx.x * 8 + (threadIdx.x >> 5);
    int lane = threadIdx.x & 31;
    if (row >= N_NODES) return;
    float s = 0.f;
    #pragma unroll
    for (int k = 0; k < 5; ++k) {
        float4 h = ((const float4*)T.p[k])[row * 32 + lane];
        const float* w = c2 + k * 128 + lane * 4;
        s += h.x * w[0] + h.y * w[1] + h.z * w[2] + h.w * w[3];
    }
    #pragma unroll
    for (int off = 16; off > 0; off >>= 1) s += __shfl_xor_sync(0xFFFFFFFFu, s, off);
    if (lane == 0) out[row] = s + g_c0[0];
}

// ---------------- launch --------------------------------------------------
extern "C" void kernel_launch(void* const* d_in, const int* in_sizes, int n_in,
                              void* d_out, int out_size) {
    const float* x  = (const float*)d_in[0];
    const int*   ei = (const int*)  d_in[1];
    const float* W0 = (const float*)d_in[2];
    const float* b0 = (const float*)d_in[3];
    const float* W1 = (const float*)d_in[4];
    const float* b1 = (const float*)d_in[5];
    const float* W2 = (const float*)d_in[6];
    const float* b2 = (const float*)d_in[7];
    const float* Wl = (const float*)d_in[8];
    const float* bl = (const float*)d_in[9];
    float* out = (float*)d_out;

    float *T1, *T2, *T3, *T4, *H, *H2;
    __half *Xh, *T1h, *T2h, *T3h, *Hh, *H2h;
    cudaGetSymbolAddress((void**)&T1,  g_T1);
    cudaGetSymbolAddress((void**)&T2,  g_T2);
    cudaGetSymbolAddress((void**)&T3,  g_T3);
    cudaGetSymbolAddress((void**)&T4,  g_T4);
    cudaGetSymbolAddress((void**)&H,   g_H);
    cudaGetSymbolAddress((void**)&H2,  g_H2);
    cudaGetSymbolAddress((void**)&Xh,  g_Xh);
    cudaGetSymbolAddress((void**)&T1h, g_T1h);
    cudaGetSymbolAddress((void**)&T2h, g_T2h);
    cudaGetSymbolAddress((void**)&T3h, g_T3h);
    cudaGetSymbolAddress((void**)&Hh,  g_Hh);
    cudaGetSymbolAddress((void**)&H2h, g_H2h);

    const int nb_n = (N_NODES + 255) / 256;
    const int nb_e = (N_EDGES + 255) / 256;
    const int spmv_blocks = (N_NODES * 32 + 255) / 256;
    const int gemm_blocks = (N_NODES + 127) / 128;
    const int conv_blocks = (N_NODES * 32 + 255) / 256;

    k_zero <<<nb_n, 256>>>();
    k_count<<<nb_e, 256>>>(ei);
    k_dinv <<<nb_n, 256>>>();
    k_scanA<<<SCAN_B, 1024>>>();
    k_scanB<<<1, 1>>>();
    k_scanC<<<SCAN_B, 1024>>>();
    k_fill <<<nb_e, 256>>>(ei);
    k_fold <<<5, 128>>>(W2, b2, Wl, bl);
    k_h16  <<<conv_blocks, 256>>>(x, Xh);

    // ---- layer 0 (T0 = x) ----
    k_spmv<<<spmv_blocks, 256>>>(Xh,  nullptr, T1, T1h, 0);
    k_spmv<<<spmv_blocks, 256>>>(T1h, x,       T2, T2h, 1);
    k_spmv<<<spmv_blocks, 256>>>(T2h, T1,      T3, T3h, 1);
    k_spmv<<<spmv_blocks, 256>>>(T3h, T2,      T4, T1h, 1);  // T4h unused; reuse T1h slot harmlessly? NO -> see below
    { A5 a; a.p[0]=x; a.p[1]=T1; a.p[2]=T2; a.p[3]=T3; a.p[4]=T4;
      k_gemm<true><<<gemm_blocks, 256>>>(a, W0, b0, H, Hh); }

    // ---- layer 1 (T0 = H) ----
    k_spmv<<<spmv_blocks, 256>>>(Hh,  nullptr, T1, T1h, 0);
    k_spmv<<<spmv_blocks, 256>>>(T1h, H,       T2, T2h, 1);
    k_spmv<<<spmv_blocks, 256>>>(T2h, T1,      T3, T3h, 1);
    k_spmv<<<spmv_blocks, 256>>>(T3h, T2,      T4, T1h, 1);
    { A5 a; a.p[0]=H; a.p[1]=T1; a.p[2]=T2; a.p[3]=T3; a.p[4]=T4;
      k_gemm<true><<<gemm_blocks, 256>>>(a, W1, b1, H2, H2h); }

    // ---- layer 2 (T0 = H2), GEMM folded into head ----
    k_spmv<<<spmv_blocks, 256>>>(H2h, nullptr, T1, T1h, 0);
    k_spmv<<<spmv_blocks, 256>>>(T1h, H2,      T2, T2h, 1);
    k_spmv<<<spmv_blocks, 256>>>(T2h, T1,      T3, T3h, 1);
    k_spmv<<<spmv_blocks, 256>>>(T3h, T2,      T4, T1h, 1);
    { A5 t; t.p[0]=H2; t.p[1]=T1; t.p[2]=T2; t.p[3]=T3; t.p[4]=T4;
      k_out<<<(N_NODES + 7) / 8, 256>>>(t, out); }
}

// round 7
// speedup vs baseline: 1.7596x; 1.7596x over previous
#include <cuda_runtime.h>
#include <cuda_fp16.h>
#include <cstdint>
#include <math.h>

#define N_NODES 50000
#define N_EDGES 800000
#define FDIM    128
#define SCAN_B  ((N_NODES + 1023) / 1024)

// ---------------- static device scratch ----------------
__device__ int    g_deg[N_NODES];
__device__ int    g_cnt[N_NODES];
__device__ int    g_ofs[N_NODES];
__device__ int    g_rp[N_NODES + 1];
__device__ float  g_dinv[N_NODES];
__device__ int    g_col[N_EDGES];
__device__ float  g_wt[N_EDGES];
__device__ int    g_bsum[SCAN_B];
__device__ int    g_bofs[SCAN_B];
__device__ float  g_T1[N_NODES * FDIM];
__device__ float  g_T2[N_NODES * FDIM];
__device__ float  g_T3[N_NODES * FDIM];
__device__ float  g_T4[N_NODES * FDIM];
__device__ float  g_H [N_NODES * FDIM];
__device__ float  g_H2[N_NODES * FDIM];
__device__ __half g_Xh [N_NODES * FDIM];
__device__ __half g_T1h[N_NODES * FDIM];
__device__ __half g_T2h[N_NODES * FDIM];
__device__ __half g_T3h[N_NODES * FDIM];
__device__ __half g_Hh [N_NODES * FDIM];
__device__ __half g_H2h[N_NODES * FDIM];
__device__ float  g_C2[5 * FDIM];
__device__ float  g_c0[1];

// ---------------- f32x2 packed helpers ----------------
typedef unsigned long long ull;
__device__ __forceinline__ ull pk2(float x, float y) {
    ull r; asm("mov.b64 %0,{%1,%2};" : "=l"(r) : "f"(x), "f"(y)); return r;
}
__device__ __forceinline__ void upk2(ull v, float& x, float& y) {
    asm("mov.b64 {%0,%1},%2;" : "=f"(x), "=f"(y) : "l"(v));
}
__device__ __forceinline__ void fma2(ull& d, ull a, ull b) {
    asm("fma.rn.f32x2 %0,%1,%2,%0;" : "+l"(d) : "l"(a), "l"(b));
}

// ---------------- preprocessing ----------------
__global__ void k_zero() {
    int i = blockIdx.x * blockDim.x + threadIdx.x;
    if (i < N_NODES) { g_deg[i] = 0; g_cnt[i] = 0; }
}

__global__ void k_count(const int* __restrict__ ei) {
    int e = blockIdx.x * blockDim.x + threadIdx.x;
    if (e < N_EDGES) {
        int s = ei[e], d = ei[N_EDGES + e];
        if (s != d) {
            atomicAdd(&g_deg[s], 1);
            atomicAdd(&g_cnt[d], 1);
        }
    }
}

__global__ void k_dinv() {
    int i = blockIdx.x * blockDim.x + threadIdx.x;
    if (i < N_NODES) {
        int dg = g_deg[i];
        g_dinv[i] = (dg > 0) ? rsqrtf((float)dg) : 0.0f;
    }
}

__global__ void k_scanA() {
    __shared__ int wsum[32];
    int tid  = threadIdx.x;
    int lane = tid & 31, wid = tid >> 5;
    int i = blockIdx.x * 1024 + tid;
    int v = (i < N_NODES) ? g_cnt[i] : 0;
    int x = v;
    #pragma unroll
    for (int off = 1; off < 32; off <<= 1) {
        int y = __shfl_up_sync(0xFFFFFFFFu, x, off);
        if (lane >= off) x += y;
    }
    if (lane == 31) wsum[wid] = x;
    __syncthreads();
    if (wid == 0) {
        int y = wsum[lane];
        #pragma unroll
        for (int off = 1; off < 32; off <<= 1) {
            int z = __shfl_up_sync(0xFFFFFFFFu, y, off);
            if (lane >= off) y += z;
        }
        wsum[lane] = y;
    }
    __syncthreads();
    int excl = x - v + (wid > 0 ? wsum[wid - 1] : 0);
    if (i < N_NODES) g_rp[i] = excl;
    if (tid == 0) g_bsum[blockIdx.x] = wsum[31];
}

__global__ void k_scanB() {
    int run = 0;
    for (int b = 0; b < SCAN_B; ++b) {
        g_bofs[b] = run;
        run += g_bsum[b];
    }
    g_rp[N_NODES] = run;
}

__global__ void k_scanC() {
    int i = blockIdx.x * 1024 + threadIdx.x;
    if (i < N_NODES) {
        int r = g_rp[i] + g_bofs[blockIdx.x];
        g_rp[i]  = r;
        g_ofs[i] = r;
    }
}

__global__ void k_fill(const int* __restrict__ ei) {
    int e = blockIdx.x * blockDim.x + threadIdx.x;
    if (e < N_EDGES) {
        int s = ei[e], d = ei[N_EDGES + e];
        if (s != d) {
            int p = atomicAdd(&g_ofs[d], 1);
            g_col[p] = s;
            g_wt[p]  = -g_dinv[s] * g_dinv[d];
        }
    }
}

__global__ void k_fold(const float* __restrict__ W2, const float* __restrict__ b2,
                       const float* __restrict__ Wl, const float* __restrict__ bl) {
    int k = blockIdx.x;
    int f = threadIdx.x;
    const float* row = W2 + ((size_t)k * 128 + f) * 128;
    float s = 0.f;
    #pragma unroll 4
    for (int w = 0; w < 128; ++w) s += row[w] * Wl[w];
    g_C2[k * 128 + f] = s;
    if (k == 0 && f == 0) {
        float c = bl[0];
        for (int w = 0; w < 128; ++w) c += b2[w] * Wl[w];
        g_c0[0] = c;
    }
}

// fp32 -> fp16 shadow conversion (for x)
__global__ void k_h16(const float* __restrict__ src, __half* __restrict__ dst) {
    int i = blockIdx.x * blockDim.x + threadIdx.x;
    if (i < N_NODES * 32) {
        float4 v = ((const float4*)src)[i];
        __half2 a = __floats2half2_rn(v.x, v.y);
        __half2 b = __floats2half2_rn(v.z, v.w);
        uint2 u;
        u.x = *reinterpret_cast<uint32_t*>(&a);
        u.y = *reinterpret_cast<uint32_t*>(&b);
        ((uint2*)dst)[i] = u;
    }
}

// ---------------- SpMV: fp16 gather, fp32 accumulate ----------------
__global__ void k_spmv(const __half* __restrict__ vinH,
                       const float* __restrict__ prev,
                       float* __restrict__ vout, __half* __restrict__ voutH,
                       int cheb) {
    int w    = (blockIdx.x * blockDim.x + threadIdx.x) >> 5;
    int lane = threadIdx.x & 31;
    if (w >= N_NODES) return;
    int beg = g_rp[w], end = g_rp[w + 1];

    float ax = 0.f, ay = 0.f, az = 0.f, aw = 0.f;
    int j = beg;
    for (; j + 1 < end; j += 2) {
        int   s0 = g_col[j],     s1 = g_col[j + 1];
        float w0 = g_wt[j],      w1 = g_wt[j + 1];
        uint2 u0 = ((const uint2*)(vinH + (size_t)s0 * 128))[lane];
        uint2 u1 = ((const uint2*)(vinH + (size_t)s1 * 128))[lane];
        float2 f00 = __half22float2(*reinterpret_cast<__half2*>(&u0.x));
        float2 f01 = __half22float2(*reinterpret_cast<__half2*>(&u0.y));
        float2 f10 = __half22float2(*reinterpret_cast<__half2*>(&u1.x));
        float2 f11 = __half22float2(*reinterpret_cast<__half2*>(&u1.y));
        ax += w0 * f00.x + w1 * f10.x;
        ay += w0 * f00.y + w1 * f10.y;
        az += w0 * f01.x + w1 * f11.x;
        aw += w0 * f01.y + w1 * f11.y;
    }
    if (j < end) {
        int   s0 = g_col[j];
        float w0 = g_wt[j];
        uint2 u0 = ((const uint2*)(vinH + (size_t)s0 * 128))[lane];
        float2 f00 = __half22float2(*reinterpret_cast<__half2*>(&u0.x));
        float2 f01 = __half22float2(*reinterpret_cast<__half2*>(&u0.y));
        ax += w0 * f00.x; ay += w0 * f00.y; az += w0 * f01.x; aw += w0 * f01.y;
    }
    float4 r;
    if (cheb) {
        float4 p = ((const float4*)prev)[w * 32 + lane];
        r.x = 2.0f * ax - p.x;
        r.y = 2.0f * ay - p.y;
        r.z = 2.0f * az - p.z;
        r.w = 2.0f * aw - p.w;
    } else {
        r.x = ax; r.y = ay; r.z = az; r.w = aw;
    }
    ((float4*)vout)[w * 32 + lane] = r;
    __half2 h0 = __floats2half2_rn(r.x, r.y);
    __half2 h1 = __floats2half2_rn(r.z, r.w);
    uint2 hu;
    hu.x = *reinterpret_cast<uint32_t*>(&h0);
    hu.y = *reinterpret_cast<uint32_t*>(&h1);
    ((uint2*)voutH)[w * 32 + lane] = hu;
}

// ---------------- fused 5-slice GEMM (round-2 layout, proven) ------------
struct A5 { const float* p[5]; };

template <bool RELU>
__global__ __launch_bounds__(256, 2)
void k_gemm(A5 A, const float* __restrict__ B,
            const float* __restrict__ bias, float* __restrict__ C,
            __half* __restrict__ Ch) {
    __shared__ float As[16][132];   // [k][m], padded
    __shared__ float Bs[16][128];   // [k][n]

    const int tid = threadIdx.x;
    const int tx  = tid & 15;   // n-tile index
    const int ty  = tid >> 4;   // m-tile index
    const int m0  = blockIdx.x * 128;

    ull accp[4][8];
    #pragma unroll
    for (int ii = 0; ii < 4; ++ii)
        #pragma unroll
        for (int j = 0; j < 8; ++j) accp[ii][j] = 0ull;

    for (int k = 0; k < 5; ++k) {
        const float* Ak = A.p[k];
        const float* Bk = B + k * 128 * 128;
        for (int kt = 0; kt < 128; kt += 16) {
            #pragma unroll
            for (int i = 0; i < 2; ++i) {
                int f = tid + i * 256;
                int row = f >> 2, cv = f & 3;
                int gm = m0 + row;
                float4 v = make_float4(0.f, 0.f, 0.f, 0.f);
                if (gm < N_NODES)
                    v = *(const float4*)(Ak + (size_t)gm * 128 + kt + cv * 4);
                As[cv * 4 + 0][row] = v.x;
                As[cv * 4 + 1][row] = v.y;
                As[cv * 4 + 2][row] = v.z;
                As[cv * 4 + 3][row] = v.w;
            }
            #pragma unroll
            for (int i = 0; i < 2; ++i) {
                int f = tid + i * 256;
                int br = f >> 5, bc = f & 31;
                *(float4*)(&Bs[br][bc * 4]) =
                    *(const float4*)(Bk + (kt + br) * 128 + bc * 4);
            }
            __syncthreads();
            #pragma unroll
            for (int kk = 0; kk < 16; ++kk) {
                ulonglong2 a01 = *(const ulonglong2*)&As[kk][ty * 8];
                ulonglong2 a23 = *(const ulonglong2*)&As[kk][ty * 8 + 4];
                ull ap[4] = { a01.x, a01.y, a23.x, a23.y };
                float b[8];
                *(float4*)(b)     = *(float4*)(&Bs[kk][tx * 8]);
                *(float4*)(b + 4) = *(float4*)(&Bs[kk][tx * 8 + 4]);
                ull bb[8];
                #pragma unroll
                for (int j = 0; j < 8; ++j) bb[j] = pk2(b[j], b[j]);
                #pragma unroll
                for (int ii = 0; ii < 4; ++ii)
                    #pragma unroll
                    for (int j = 0; j < 8; ++j)
                        fma2(accp[ii][j], ap[ii], bb[j]);
            }
            __syncthreads();
        }
    }
    // epilogue: unpack, bias (+relu), store fp32 + fp16 shadow
    #pragma unroll
    for (int ii = 0; ii < 4; ++ii) {
        float r0[8], r1[8];
        #pragma unroll
        for (int j = 0; j < 8; ++j) upk2(accp[ii][j], r0[j], r1[j]);
        #pragma unroll
        for (int h = 0; h < 2; ++h) {
            float* rr = h ? r1 : r0;
            int gm = m0 + ty * 8 + 2 * ii + h;
            if (gm >= N_NODES) continue;
            #pragma unroll
            for (int j = 0; j < 8; j += 4) {
                float4 r;
                r.x = rr[j + 0] + bias[tx * 8 + j + 0];
                r.y = rr[j + 1] + bias[tx * 8 + j + 1];
                r.z = rr[j + 2] + bias[tx * 8 + j + 2];
                r.w = rr[j + 3] + bias[tx * 8 + j + 3];
                if (RELU) {
                    r.x = fmaxf(r.x, 0.f); r.y = fmaxf(r.y, 0.f);
                    r.z = fmaxf(r.z, 0.f); r.w = fmaxf(r.w, 0.f);
                }
                *(float4*)(C + (size_t)gm * 128 + tx * 8 + j) = r;
                __half2 h0 = __floats2half2_rn(r.x, r.y);
                __half2 h1 = __floats2half2_rn(r.z, r.w);
                uint2 hu;
                hu.x = *reinterpret_cast<uint32_t*>(&h0);
                hu.y = *reinterpret_cast<uint32_t*>(&h1);
                *(uint2*)(Ch + (size_t)gm * 128 + tx * 8 + j) = hu;
            }
        }
    }
}

// ---------------- fused layer-2 + head ----------------
__global__ void k_out(A5 T, float* __restrict__ out) {
    __shared__ float c2[5 * 128];
    for (int i = threadIdx.x; i < 5 * 128; i += blockDim.x) c2[i] = g_C2[i];
    __syncthreads();
    int row  = blockIdx.x * 8 + (threadIdx.x >> 5);
    int lane = threadIdx.x & 31;
    if (row >= N_NODES) return;
    float s = 0.f;
    #pragma unroll
    for (int k = 0; k < 5; ++k) {
        float4 h = ((const float4*)T.p[k])[row * 32 + lane];
        const float* w = c2 + k * 128 + lane * 4;
        s += h.x * w[0] + h.y * w[1] + h.z * w[2] + h.w * w[3];
    }
    #pragma unroll
    for (int off = 16; off > 0; off >>= 1) s += __shfl_xor_sync(0xFFFFFFFFu, s, off);
    if (lane == 0) out[row] = s + g_c0[0];
}

// ---------------- launch --------------------------------------------------
extern "C" void kernel_launch(void* const* d_in, const int* in_sizes, int n_in,
                              void* d_out, int out_size) {
    const float* x  = (const float*)d_in[0];
    const int*   ei = (const int*)  d_in[1];
    const float* W0 = (const float*)d_in[2];
    const float* b0 = (const float*)d_in[3];
    const float* W1 = (const float*)d_in[4];
    const float* b1 = (const float*)d_in[5];
    const float* W2 = (const float*)d_in[6];
    const float* b2 = (const float*)d_in[7];
    const float* Wl = (const float*)d_in[8];
    const float* bl = (const float*)d_in[9];
    float* out = (float*)d_out;

    float *T1, *T2, *T3, *T4, *H, *H2;
    __half *Xh, *T1h, *T2h, *T3h, *Hh, *H2h;
    cudaGetSymbolAddress((void**)&T1,  g_T1);
    cudaGetSymbolAddress((void**)&T2,  g_T2);
    cudaGetSymbolAddress((void**)&T3,  g_T3);
    cudaGetSymbolAddress((void**)&T4,  g_T4);
    cudaGetSymbolAddress((void**)&H,   g_H);
    cudaGetSymbolAddress((void**)&H2,  g_H2);
    cudaGetSymbolAddress((void**)&Xh,  g_Xh);
    cudaGetSymbolAddress((void**)&T1h, g_T1h);
    cudaGetSymbolAddress((void**)&T2h, g_T2h);
    cudaGetSymbolAddress((void**)&T3h, g_T3h);
    cudaGetSymbolAddress((void**)&Hh,  g_Hh);
    cudaGetSymbolAddress((void**)&H2h, g_H2h);

    const int nb_n = (N_NODES + 255) / 256;
    const int nb_e = (N_EDGES + 255) / 256;
    const int spmv_blocks = (N_NODES * 32 + 255) / 256;
    const int gemm_blocks = (N_NODES + 127) / 128;
    const int conv_blocks = (N_NODES * 32 + 255) / 256;

    k_zero <<<nb_n, 256>>>();
    k_count<<<nb_e, 256>>>(ei);
    k_dinv <<<nb_n, 256>>>();
    k_scanA<<<SCAN_B, 1024>>>();
    k_scanB<<<1, 1>>>();
    k_scanC<<<SCAN_B, 1024>>>();
    k_fill <<<nb_e, 256>>>(ei);
    k_fold <<<5, 128>>>(W2, b2, Wl, bl);
    k_h16  <<<conv_blocks, 256>>>(x, Xh);

    // ---- layer 0 (T0 = x) ----
    k_spmv<<<spmv_blocks, 256>>>(Xh,  nullptr, T1, T1h, 0);
    k_spmv<<<spmv_blocks, 256>>>(T1h, x,       T2, T2h, 1);
    k_spmv<<<spmv_blocks, 256>>>(T2h, T1,      T3, T3h, 1);
    k_spmv<<<spmv_blocks, 256>>>(T3h, T2,      T4, T1h, 1);  // T4 shadow never gathered; T1h dead here
    { A5 a; a.p[0]=x; a.p[1]=T1; a.p[2]=T2; a.p[3]=T3; a.p[4]=T4;
      k_gemm<true><<<gemm_blocks, 256>>>(a, W0, b0, H, Hh); }

    // ---- layer 1 (T0 = H) ----
    k_spmv<<<spmv_blocks, 256>>>(Hh,  nullptr, T1, T1h, 0);
    k_spmv<<<spmv_blocks, 256>>>(T1h, H,       T2, T2h, 1);
    k_spmv<<<spmv_blocks, 256>>>(T2h, T1,      T3, T3h, 1);
    k_spmv<<<spmv_blocks, 256>>>(T3h, T2,      T4, T1h, 1);
    { A5 a; a.p[0]=H; a.p[1]=T1; a.p[2]=T2; a.p[3]=T3; a.p[4]=T4;
      k_gemm<true><<<gemm_blocks, 256>>>(a, W1, b1, H2, H2h); }

    // ---- layer 2 (T0 = H2), GEMM folded into head ----
    k_spmv<<<spmv_blocks, 256>>>(H2h, nullptr, T1, T1h, 0);
    k_spmv<<<spmv_blocks, 256>>>(T1h, H2,      T2, T2h, 1);
    k_spmv<<<spmv_blocks, 256>>>(T2h, T1,      T3, T3h, 1);
    k_spmv<<<spmv_blocks, 256>>>(T3h, T2,      T4, T1h, 1);
    { A5 t; t.p[0]=H2; t.p[1]=T1; t.p[2]=T2; t.p[3]=T3; t.p[4]=T4;
      k_out<<<(N_NODES + 7) / 8, 256>>>(t, out); }
}

// round 8
// speedup vs baseline: 2.3732x; 1.3487x over previous
#include <cuda_runtime.h>
#include <cuda_fp16.h>
#include <cstdint>
#include <math.h>

#define N_NODES 50000
#define N_EDGES 800000
#define FDIM    128
#define SCAN_B  ((N_NODES + 1023) / 1024)
#define AP      40     // padded halves per smem row (80B)

// ---------------- static device scratch ----------------
__device__ int    g_deg[N_NODES];
__device__ int    g_cnt[N_NODES];
__device__ int    g_ofs[N_NODES];
__device__ int    g_rp[N_NODES + 1];
__device__ float  g_dinv[N_NODES];
__device__ int    g_col[N_EDGES];
__device__ float  g_wt[N_EDGES];
__device__ int    g_bsum[SCAN_B];
__device__ int    g_bofs[SCAN_B];
__device__ float  g_T1[N_NODES * FDIM];
__device__ float  g_T2[N_NODES * FDIM];
__device__ float  g_T3[N_NODES * FDIM];
__device__ float  g_T4[N_NODES * FDIM];
__device__ float  g_H [N_NODES * FDIM];
__device__ float  g_H2[N_NODES * FDIM];
__device__ __half g_Xh [N_NODES * FDIM];
__device__ __half g_T1h[N_NODES * FDIM];
__device__ __half g_T2h[N_NODES * FDIM];
__device__ __half g_T3h[N_NODES * FDIM];
__device__ __half g_Hh [N_NODES * FDIM];
__device__ __half g_H2h[N_NODES * FDIM];
__device__ __half g_W0th[5 * 128 * 128];   // W0 transposed [s][n][k], hi
__device__ __half g_W0tl[5 * 128 * 128];   // lo
__device__ __half g_W1th[5 * 128 * 128];
__device__ __half g_W1tl[5 * 128 * 128];
__device__ float  g_C2[5 * FDIM];
__device__ float  g_c0[1];

// ---------------- preprocessing ----------------
__global__ void k_zero() {
    int i = blockIdx.x * blockDim.x + threadIdx.x;
    if (i < N_NODES) { g_deg[i] = 0; g_cnt[i] = 0; }
}

__global__ void k_count(const int* __restrict__ ei) {
    int e = blockIdx.x * blockDim.x + threadIdx.x;
    if (e < N_EDGES) {
        int s = ei[e], d = ei[N_EDGES + e];
        if (s != d) {
            atomicAdd(&g_deg[s], 1);
            atomicAdd(&g_cnt[d], 1);
        }
    }
}

__global__ void k_dinv() {
    int i = blockIdx.x * blockDim.x + threadIdx.x;
    if (i < N_NODES) {
        int dg = g_deg[i];
        g_dinv[i] = (dg > 0) ? rsqrtf((float)dg) : 0.0f;
    }
}

__global__ void k_scanA() {
    __shared__ int wsum[32];
    int tid  = threadIdx.x;
    int lane = tid & 31, wid = tid >> 5;
    int i = blockIdx.x * 1024 + tid;
    int v = (i < N_NODES) ? g_cnt[i] : 0;
    int x = v;
    #pragma unroll
    for (int off = 1; off < 32; off <<= 1) {
        int y = __shfl_up_sync(0xFFFFFFFFu, x, off);
        if (lane >= off) x += y;
    }
    if (lane == 31) wsum[wid] = x;
    __syncthreads();
    if (wid == 0) {
        int y = wsum[lane];
        #pragma unroll
        for (int off = 1; off < 32; off <<= 1) {
            int z = __shfl_up_sync(0xFFFFFFFFu, y, off);
            if (lane >= off) y += z;
        }
        wsum[lane] = y;
    }
    __syncthreads();
    int excl = x - v + (wid > 0 ? wsum[wid - 1] : 0);
    if (i < N_NODES) g_rp[i] = excl;
    if (tid == 0) g_bsum[blockIdx.x] = wsum[31];
}

__global__ void k_scanB() {
    int run = 0;
    for (int b = 0; b < SCAN_B; ++b) {
        g_bofs[b] = run;
        run += g_bsum[b];
    }
    g_rp[N_NODES] = run;
}

__global__ void k_scanC() {
    int i = blockIdx.x * 1024 + threadIdx.x;
    if (i < N_NODES) {
        int r = g_rp[i] + g_bofs[blockIdx.x];
        g_rp[i]  = r;
        g_ofs[i] = r;
    }
}

__global__ void k_fill(const int* __restrict__ ei) {
    int e = blockIdx.x * blockDim.x + threadIdx.x;
    if (e < N_EDGES) {
        int s = ei[e], d = ei[N_EDGES + e];
        if (s != d) {
            int p = atomicAdd(&g_ofs[d], 1);
            g_col[p] = s;
            g_wt[p]  = -g_dinv[s] * g_dinv[d];
        }
    }
}

__global__ void k_fold(const float* __restrict__ W2, const float* __restrict__ b2,
                       const float* __restrict__ Wl, const float* __restrict__ bl) {
    int k = blockIdx.x;
    int f = threadIdx.x;
    const float* row = W2 + ((size_t)k * 128 + f) * 128;
    float s = 0.f;
    #pragma unroll 4
    for (int w = 0; w < 128; ++w) s += row[w] * Wl[w];
    g_C2[k * 128 + f] = s;
    if (k == 0 && f == 0) {
        float c = bl[0];
        for (int w = 0; w < 128; ++w) c += b2[w] * Wl[w];
        g_c0[0] = c;
    }
}

// split W [5][k=128][n=128] fp32 -> transposed [5][n][k] fp16 hi/lo
__global__ void k_wsplit(const float* __restrict__ W,
                         __half* __restrict__ Wh, __half* __restrict__ Wl) {
    int o = blockIdx.x * 256 + threadIdx.x;
    if (o < 5 * 128 * 128) {
        int s = o >> 14, r = o & 16383, n = r >> 7, k = r & 127;
        float w = W[s * 16384 + k * 128 + n];
        __half h = __float2half_rn(w);
        Wh[o] = h;
        Wl[o] = __float2half_rn(w - __half2float(h));
    }
}

// fp32 -> fp16 shadow conversion (for x)
__global__ void k_h16(const float* __restrict__ src, __half* __restrict__ dst) {
    int i = blockIdx.x * blockDim.x + threadIdx.x;
    if (i < N_NODES * 32) {
        float4 v = ((const float4*)src)[i];
        __half2 a = __floats2half2_rn(v.x, v.y);
        __half2 b = __floats2half2_rn(v.z, v.w);
        uint2 u;
        u.x = *reinterpret_cast<uint32_t*>(&a);
        u.y = *reinterpret_cast<uint32_t*>(&b);
        ((uint2*)dst)[i] = u;
    }
}

// ---------------- SpMV: fp16 gather, fp32 accumulate ----------------
__global__ void k_spmv(const __half* __restrict__ vinH,
                       const float* __restrict__ prev,
                       float* __restrict__ vout, __half* __restrict__ voutH,
                       int cheb) {
    int w    = (blockIdx.x * blockDim.x + threadIdx.x) >> 5;
    int lane = threadIdx.x & 31;
    if (w >= N_NODES) return;
    int beg = g_rp[w], end = g_rp[w + 1];

    float ax = 0.f, ay = 0.f, az = 0.f, aw = 0.f;
    int j = beg;
    for (; j + 1 < end; j += 2) {
        int   s0 = g_col[j],     s1 = g_col[j + 1];
        float w0 = g_wt[j],      w1 = g_wt[j + 1];
        uint2 u0 = ((const uint2*)(vinH + (size_t)s0 * 128))[lane];
        uint2 u1 = ((const uint2*)(vinH + (size_t)s1 * 128))[lane];
        float2 f00 = __half22float2(*reinterpret_cast<__half2*>(&u0.x));
        float2 f01 = __half22float2(*reinterpret_cast<__half2*>(&u0.y));
        float2 f10 = __half22float2(*reinterpret_cast<__half2*>(&u1.x));
        float2 f11 = __half22float2(*reinterpret_cast<__half2*>(&u1.y));
        ax += w0 * f00.x + w1 * f10.x;
        ay += w0 * f00.y + w1 * f10.y;
        az += w0 * f01.x + w1 * f11.x;
        aw += w0 * f01.y + w1 * f11.y;
    }
    if (j < end) {
        int   s0 = g_col[j];
        float w0 = g_wt[j];
        uint2 u0 = ((const uint2*)(vinH + (size_t)s0 * 128))[lane];
        float2 f00 = __half22float2(*reinterpret_cast<__half2*>(&u0.x));
        float2 f01 = __half22float2(*reinterpret_cast<__half2*>(&u0.y));
        ax += w0 * f00.x; ay += w0 * f00.y; az += w0 * f01.x; aw += w0 * f01.y;
    }
    float4 r;
    if (cheb) {
        float4 p = ((const float4*)prev)[w * 32 + lane];
        r.x = 2.0f * ax - p.x;
        r.y = 2.0f * ay - p.y;
        r.z = 2.0f * az - p.z;
        r.w = 2.0f * aw - p.w;
    } else {
        r.x = ax; r.y = ay; r.z = az; r.w = aw;
    }
    ((float4*)vout)[w * 32 + lane] = r;
    __half2 h0 = __floats2half2_rn(r.x, r.y);
    __half2 h1 = __floats2half2_rn(r.z, r.w);
    uint2 hu;
    hu.x = *reinterpret_cast<uint32_t*>(&h0);
    hu.y = *reinterpret_cast<uint32_t*>(&h1);
    ((uint2*)voutH)[w * 32 + lane] = hu;
}

// ---------------- tensor-core fused 5-slice GEMM (mma.sync, fp16 split) --
struct A5 { const float* p[5]; };

__device__ __forceinline__ void mma16816(float* d, const uint32_t* a, const uint32_t* b) {
    asm volatile(
        "mma.sync.aligned.m16n8k16.row.col.f32.f16.f16.f32 "
        "{%0,%1,%2,%3}, {%4,%5,%6,%7}, {%8,%9}, {%0,%1,%2,%3};"
        : "+f"(d[0]), "+f"(d[1]), "+f"(d[2]), "+f"(d[3])
        : "r"(a[0]), "r"(a[1]), "r"(a[2]), "r"(a[3]), "r"(b[0]), "r"(b[1]));
}

template <bool RELU>
__global__ __launch_bounds__(256, 2)
void k_gemm_mma(A5 A, const __half* __restrict__ Bh, const __half* __restrict__ Bl,
                const float* __restrict__ bias, float* __restrict__ C,
                __half* __restrict__ Ch) {
    __shared__ __align__(16) __half sAh[128 * AP];
    __shared__ __align__(16) __half sAl[128 * AP];
    __shared__ __align__(16) __half sBh[128 * AP];
    __shared__ __align__(16) __half sBl[128 * AP];

    const int tid  = threadIdx.x;
    const int wid  = tid >> 5, lane = tid & 31;
    const int g    = lane >> 2, t = lane & 3;
    const int wm   = wid & 3;        // m warp: 32 rows
    const int wn   = wid >> 2;       // n warp: 64 cols
    const int m0   = blockIdx.x * 128;

    float acc[2][8][4];
    #pragma unroll
    for (int mt = 0; mt < 2; ++mt)
        #pragma unroll
        for (int nt = 0; nt < 8; ++nt)
            #pragma unroll
            for (int q = 0; q < 4; ++q) acc[mt][nt][q] = 0.f;

    const int r  = tid >> 1;          // A row / B n-col this thread stages
    const int hf = tid & 1;           // which 16-half chunk of the 32-k row

    #pragma unroll 1
    for (int c = 0; c < 20; ++c) {
        const int s  = c >> 2;
        const int k0 = (c & 3) * 32;
        __syncthreads();

        // ---- stage A (fp32 -> hi/lo fp16) ----
        {
            float f[16];
            const int gm = m0 + r;
            if (gm < N_NODES) {
                const float4* src = (const float4*)(A.p[s] + (size_t)gm * 128 + k0 + hf * 16);
                #pragma unroll
                for (int i = 0; i < 4; ++i) *(float4*)&f[i * 4] = src[i];
            } else {
                #pragma unroll
                for (int i = 0; i < 16; ++i) f[i] = 0.f;
            }
            uint32_t hb[8], lb[8];
            #pragma unroll
            for (int i = 0; i < 8; ++i) {
                __half2 h2 = __floats2half2_rn(f[2 * i], f[2 * i + 1]);
                float2  hc = __half22float2(h2);
                __half2 l2 = __floats2half2_rn(f[2 * i] - hc.x, f[2 * i + 1] - hc.y);
                hb[i] = *reinterpret_cast<uint32_t*>(&h2);
                lb[i] = *reinterpret_cast<uint32_t*>(&l2);
            }
            const int o = r * AP + hf * 16;
            *(uint4*)&sAh[o]     = *(uint4*)&hb[0];
            *(uint4*)&sAh[o + 8] = *(uint4*)&hb[4];
            *(uint4*)&sAl[o]     = *(uint4*)&lb[0];
            *(uint4*)&sAl[o + 8] = *(uint4*)&lb[4];
        }
        // ---- stage B (pre-split fp16 [s][n][k]) ----
        {
            const size_t gb = (size_t)s * 16384 + (size_t)r * 128 + k0 + hf * 16;
            const uint4* sh = (const uint4*)(Bh + gb);
            const uint4* sl = (const uint4*)(Bl + gb);
            const int o = r * AP + hf * 16;
            *(uint4*)&sBh[o]     = sh[0];
            *(uint4*)&sBh[o + 8] = sh[1];
            *(uint4*)&sBl[o]     = sl[0];
            *(uint4*)&sBl[o + 8] = sl[1];
        }
        __syncthreads();

        // ---- compute: 2 k-steps of 16, products hh + lh + hl ----
        #pragma unroll
        for (int ks = 0; ks < 2; ++ks) {
            const int kb = ks * 16 + 2 * t;
            uint32_t bf[8][2], ah[2][4], al[2][4];
            #pragma unroll
            for (int nt = 0; nt < 8; ++nt) {
                const int nb = (wn * 64 + nt * 8 + g) * AP + kb;
                bf[nt][0] = *(const uint32_t*)&sBh[nb];
                bf[nt][1] = *(const uint32_t*)&sBh[nb + 8];
            }
            #pragma unroll
            for (int mt = 0; mt < 2; ++mt) {
                const int rb = (wm * 32 + mt * 16 + g) * AP + kb;
                ah[mt][0] = *(const uint32_t*)&sAh[rb];
                ah[mt][1] = *(const uint32_t*)&sAh[rb + 8 * AP];
                ah[mt][2] = *(const uint32_t*)&sAh[rb + 8];
                ah[mt][3] = *(const uint32_t*)&sAh[rb + 8 * AP + 8];
                al[mt][0] = *(const uint32_t*)&sAl[rb];
                al[mt][1] = *(const uint32_t*)&sAl[rb + 8 * AP];
                al[mt][2] = *(const uint32_t*)&sAl[rb + 8];
                al[mt][3] = *(const uint32_t*)&sAl[rb + 8 * AP + 8];
            }
            #pragma unroll
            for (int mt = 0; mt < 2; ++mt)
                #pragma unroll
                for (int nt = 0; nt < 8; ++nt) mma16816(acc[mt][nt], ah[mt], bf[nt]);
            #pragma unroll
            for (int mt = 0; mt < 2; ++mt)
                #pragma unroll
                for (int nt = 0; nt < 8; ++nt) mma16816(acc[mt][nt], al[mt], bf[nt]);
            #pragma unroll
            for (int nt = 0; nt < 8; ++nt) {
                const int nb = (wn * 64 + nt * 8 + g) * AP + kb;
                bf[nt][0] = *(const uint32_t*)&sBl[nb];
                bf[nt][1] = *(const uint32_t*)&sBl[nb + 8];
            }
            #pragma unroll
            for (int mt = 0; mt < 2; ++mt)
                #pragma unroll
                for (int nt = 0; nt < 8; ++nt) mma16816(acc[mt][nt], ah[mt], bf[nt]);
        }
    }

    // ---- epilogue: bias (+relu), fp32 + fp16 shadow ----
    #pragma unroll
    for (int mt = 0; mt < 2; ++mt) {
        #pragma unroll
        for (int half = 0; half < 2; ++half) {
            const int row = m0 + wm * 32 + mt * 16 + g + half * 8;
            if (row < N_NODES) {
                #pragma unroll
                for (int nt = 0; nt < 8; ++nt) {
                    const int col = wn * 64 + nt * 8 + 2 * t;
                    float v0 = acc[mt][nt][half * 2 + 0] + __ldg(bias + col);
                    float v1 = acc[mt][nt][half * 2 + 1] + __ldg(bias + col + 1);
                    if (RELU) { v0 = fmaxf(v0, 0.f); v1 = fmaxf(v1, 0.f); }
                    float2 o; o.x = v0; o.y = v1;
                    *(float2*)(C + (size_t)row * 128 + col) = o;
                    __half2 h2 = __floats2half2_rn(v0, v1);
                    *(uint32_t*)(Ch + (size_t)row * 128 + col) =
                        *reinterpret_cast<uint32_t*>(&h2);
                }
            }
        }
    }
}

// ---------------- fused layer-2 + head ----------------
__global__ void k_out(A5 T, float* __restrict__ out) {
    __shared__ float c2[5 * 128];
    for (int i = threadIdx.x; i < 5 * 128; i += blockDim.x) c2[i] = g_C2[i];
    __syncthreads();
    int row  = blockIdx.x * 8 + (threadIdx.x >> 5);
    int lane = threadIdx.x & 31;
    if (row >= N_NODES) return;
    float s = 0.f;
    #pragma unroll
    for (int k = 0; k < 5; ++k) {
        float4 h = ((const float4*)T.p[k])[row * 32 + lane];
        const float* w = c2 + k * 128 + lane * 4;
        s += h.x * w[0] + h.y * w[1] + h.z * w[2] + h.w * w[3];
    }
    #pragma unroll
    for (int off = 16; off > 0; off >>= 1) s += __shfl_xor_sync(0xFFFFFFFFu, s, off);
    if (lane == 0) out[row] = s + g_c0[0];
}

// ---------------- launch --------------------------------------------------
extern "C" void kernel_launch(void* const* d_in, const int* in_sizes, int n_in,
                              void* d_out, int out_size) {
    const float* x  = (const float*)d_in[0];
    const int*   ei = (const int*)  d_in[1];
    const float* W0 = (const float*)d_in[2];
    const float* b0 = (const float*)d_in[3];
    const float* W1 = (const float*)d_in[4];
    const float* b1 = (const float*)d_in[5];
    const float* W2 = (const float*)d_in[6];
    const float* b2 = (const float*)d_in[7];
    const float* Wl = (const float*)d_in[8];
    const float* bl = (const float*)d_in[9];
    float* out = (float*)d_out;

    float *T1, *T2, *T3, *T4, *H, *H2;
    __half *Xh, *T1h, *T2h, *T3h, *Hh, *H2h;
    __half *W0th, *W0tl, *W1th, *W1tl;
    cudaGetSymbolAddress((void**)&T1,   g_T1);
    cudaGetSymbolAddress((void**)&T2,   g_T2);
    cudaGetSymbolAddress((void**)&T3,   g_T3);
    cudaGetSymbolAddress((void**)&T4,   g_T4);
    cudaGetSymbolAddress((void**)&H,    g_H);
    cudaGetSymbolAddress((void**)&H2,   g_H2);
    cudaGetSymbolAddress((void**)&Xh,   g_Xh);
    cudaGetSymbolAddress((void**)&T1h,  g_T1h);
    cudaGetSymbolAddress((void**)&T2h,  g_T2h);
    cudaGetSymbolAddress((void**)&T3h,  g_T3h);
    cudaGetSymbolAddress((void**)&Hh,   g_Hh);
    cudaGetSymbolAddress((void**)&H2h,  g_H2h);
    cudaGetSymbolAddress((void**)&W0th, g_W0th);
    cudaGetSymbolAddress((void**)&W0tl, g_W0tl);
    cudaGetSymbolAddress((void**)&W1th, g_W1th);
    cudaGetSymbolAddress((void**)&W1tl, g_W1tl);

    const int nb_n = (N_NODES + 255) / 256;
    const int nb_e = (N_EDGES + 255) / 256;
    const int spmv_blocks = (N_NODES * 32 + 255) / 256;
    const int gemm_blocks = (N_NODES + 127) / 128;
    const int conv_blocks = (N_NODES * 32 + 255) / 256;
    const int wsp_blocks  = (5 * 128 * 128 + 255) / 256;

    k_zero  <<<nb_n, 256>>>();
    k_count <<<nb_e, 256>>>(ei);
    k_dinv  <<<nb_n, 256>>>();
    k_scanA <<<SCAN_B, 1024>>>();
    k_scanB <<<1, 1>>>();
    k_scanC <<<SCAN_B, 1024>>>();
    k_fill  <<<nb_e, 256>>>(ei);
    k_fold  <<<5, 128>>>(W2, b2, Wl, bl);
    k_wsplit<<<wsp_blocks, 256>>>(W0, W0th, W0tl);
    k_wsplit<<<wsp_blocks, 256>>>(W1, W1th, W1tl);
    k_h16   <<<conv_blocks, 256>>>(x, Xh);

    // ---- layer 0 (T0 = x) ----
    k_spmv<<<spmv_blocks, 256>>>(Xh,  nullptr, T1, T1h, 0);
    k_spmv<<<spmv_blocks, 256>>>(T1h, x,       T2, T2h, 1);
    k_spmv<<<spmv_blocks, 256>>>(T2h, T1,      T3, T3h, 1);
    k_spmv<<<spmv_blocks, 256>>>(T3h, T2,      T4, T1h, 1);  // T4 shadow never gathered
    { A5 a; a.p[0]=x; a.p[1]=T1; a.p[2]=T2; a.p[3]=T3; a.p[4]=T4;
      k_gemm_mma<true><<<gemm_blocks, 256>>>(a, W0th, W0tl, b0, H, Hh); }

    // ---- layer 1 (T0 = H) ----
    k_spmv<<<spmv_blocks, 256>>>(Hh,  nullptr, T1, T1h, 0);
    k_spmv<<<spmv_blocks, 256>>>(T1h, H,       T2, T2h, 1);
    k_spmv<<<spmv_blocks, 256>>>(T2h, T1,      T3, T3h, 1);
    k_spmv<<<spmv_blocks, 256>>>(T3h, T2,      T4, T1h, 1);
    { A5 a; a.p[0]=H; a.p[1]=T1; a.p[2]=T2; a.p[3]=T3; a.p[4]=T4;
      k_gemm_mma<true><<<gemm_blocks, 256>>>(a, W1th, W1tl, b1, H2, H2h); }

    // ---- layer 2 (T0 = H2), GEMM folded into head ----
    k_spmv<<<spmv_blocks, 256>>>(H2h, nullptr, T1, T1h, 0);
    k_spmv<<<spmv_blocks, 256>>>(T1h, H2,      T2, T2h, 1);
    k_spmv<<<spmv_blocks, 256>>>(T2h, T1,      T3, T3h, 1);
    k_spmv<<<spmv_blocks, 256>>>(T3h, T2,      T4, T1h, 1);
    { A5 t; t.p[0]=H2; t.p[1]=T1; t.p[2]=T2; t.p[3]=T3; t.p[4]=T4;
      k_out<<<(N_NODES + 7) / 8, 256>>>(t, out); }
}

// round 9
// speedup vs baseline: 2.5281x; 1.0652x over previous
#include <cuda_runtime.h>
#include <cuda_fp16.h>
#include <cstdint>
#include <math.h>

#define N_NODES 50000
#define N_EDGES 800000
#define FDIM    128
#define SCAN_B  ((N_NODES + 1023) / 1024)
#define AP      40     // padded halves per smem row (80B)

// ---------------- static device scratch ----------------
__device__ int    g_deg[N_NODES];
__device__ int    g_cnt[N_NODES];
__device__ int    g_ofs[N_NODES];
__device__ int    g_rp[N_NODES + 1];
__device__ float  g_dinv[N_NODES];
__device__ int    g_col[N_EDGES];
__device__ float  g_wt[N_EDGES];
__device__ int    g_bsum[SCAN_B];
__device__ int    g_bofs[SCAN_B];
__device__ float  g_T1[N_NODES * FDIM];
__device__ float  g_T2[N_NODES * FDIM];
__device__ float  g_T3[N_NODES * FDIM];
__device__ float  g_T4[N_NODES * FDIM];
__device__ float  g_H [N_NODES * FDIM];
__device__ float  g_H2[N_NODES * FDIM];
__device__ __half g_Xh [N_NODES * FDIM];
__device__ __half g_T1h[N_NODES * FDIM];
__device__ __half g_T2h[N_NODES * FDIM];
__device__ __half g_T3h[N_NODES * FDIM];
__device__ __half g_Hh [N_NODES * FDIM];
__device__ __half g_H2h[N_NODES * FDIM];
__device__ __half g_W0th[5 * 128 * 128];   // W0 transposed [s][n][k], hi
__device__ __half g_W0tl[5 * 128 * 128];   // lo
__device__ __half g_W1th[5 * 128 * 128];
__device__ __half g_W1tl[5 * 128 * 128];
__device__ float  g_C2[5 * FDIM];
__device__ float  g_c0[1];

// ---------------- preprocessing ----------------
__global__ void k_zero() {
    int i = blockIdx.x * blockDim.x + threadIdx.x;
    if (i < N_NODES) { g_deg[i] = 0; g_cnt[i] = 0; }
}

__global__ void k_count(const int* __restrict__ ei) {
    int e = blockIdx.x * blockDim.x + threadIdx.x;
    if (e < N_EDGES) {
        int s = ei[e], d = ei[N_EDGES + e];
        if (s != d) {
            atomicAdd(&g_deg[s], 1);
            atomicAdd(&g_cnt[d], 1);
        }
    }
}

__global__ void k_dinv() {
    int i = blockIdx.x * blockDim.x + threadIdx.x;
    if (i < N_NODES) {
        int dg = g_deg[i];
        g_dinv[i] = (dg > 0) ? rsqrtf((float)dg) : 0.0f;
    }
}

__global__ void k_scanA() {
    __shared__ int wsum[32];
    int tid  = threadIdx.x;
    int lane = tid & 31, wid = tid >> 5;
    int i = blockIdx.x * 1024 + tid;
    int v = (i < N_NODES) ? g_cnt[i] : 0;
    int x = v;
    #pragma unroll
    for (int off = 1; off < 32; off <<= 1) {
        int y = __shfl_up_sync(0xFFFFFFFFu, x, off);
        if (lane >= off) x += y;
    }
    if (lane == 31) wsum[wid] = x;
    __syncthreads();
    if (wid == 0) {
        int y = wsum[lane];
        #pragma unroll
        for (int off = 1; off < 32; off <<= 1) {
            int z = __shfl_up_sync(0xFFFFFFFFu, y, off);
            if (lane >= off) y += z;
        }
        wsum[lane] = y;
    }
    __syncthreads();
    int excl = x - v + (wid > 0 ? wsum[wid - 1] : 0);
    if (i < N_NODES) g_rp[i] = excl;
    if (tid == 0) g_bsum[blockIdx.x] = wsum[31];
}

__global__ void k_scanB() {
    int run = 0;
    for (int b = 0; b < SCAN_B; ++b) {
        g_bofs[b] = run;
        run += g_bsum[b];
    }
    g_rp[N_NODES] = run;
}

__global__ void k_scanC() {
    int i = blockIdx.x * 1024 + threadIdx.x;
    if (i < N_NODES) {
        int r = g_rp[i] + g_bofs[blockIdx.x];
        g_rp[i]  = r;
        g_ofs[i] = r;
    }
}

__global__ void k_fill(const int* __restrict__ ei) {
    int e = blockIdx.x * blockDim.x + threadIdx.x;
    if (e < N_EDGES) {
        int s = ei[e], d = ei[N_EDGES + e];
        if (s != d) {
            int p = atomicAdd(&g_ofs[d], 1);
            g_col[p] = s;
            g_wt[p]  = -g_dinv[s] * g_dinv[d];
        }
    }
}

__global__ void k_fold(const float* __restrict__ W2, const float* __restrict__ b2,
                       const float* __restrict__ Wl, const float* __restrict__ bl) {
    int k = blockIdx.x;
    int f = threadIdx.x;
    const float* row = W2 + ((size_t)k * 128 + f) * 128;
    float s = 0.f;
    #pragma unroll 4
    for (int w = 0; w < 128; ++w) s += row[w] * Wl[w];
    g_C2[k * 128 + f] = s;
    if (k == 0 && f == 0) {
        float c = bl[0];
        for (int w = 0; w < 128; ++w) c += b2[w] * Wl[w];
        g_c0[0] = c;
    }
}

// split W [5][k=128][n=128] fp32 -> transposed [5][n][k] fp16 hi/lo
__global__ void k_wsplit(const float* __restrict__ W,
                         __half* __restrict__ Wh, __half* __restrict__ Wl) {
    int o = blockIdx.x * 256 + threadIdx.x;
    if (o < 5 * 128 * 128) {
        int s = o >> 14, r = o & 16383, n = r >> 7, k = r & 127;
        float w = W[s * 16384 + k * 128 + n];
        __half h = __float2half_rn(w);
        Wh[o] = h;
        Wl[o] = __float2half_rn(w - __half2float(h));
    }
}

// fp32 -> fp16 shadow conversion (for x)
__global__ void k_h16(const float* __restrict__ src, __half* __restrict__ dst) {
    int i = blockIdx.x * blockDim.x + threadIdx.x;
    if (i < N_NODES * 32) {
        float4 v = ((const float4*)src)[i];
        __half2 a = __floats2half2_rn(v.x, v.y);
        __half2 b = __floats2half2_rn(v.z, v.w);
        uint2 u;
        u.x = *reinterpret_cast<uint32_t*>(&a);
        u.y = *reinterpret_cast<uint32_t*>(&b);
        ((uint2*)dst)[i] = u;
    }
}

// ---------------- gather core: acc += sum_j w_j * vinH[col_j] ------------
__device__ __forceinline__ void gather_row(
    const __half* __restrict__ vinH, int beg, int end, int lane,
    float& ax, float& ay, float& az, float& aw)
{
    int j = beg;
    for (; j + 3 < end; j += 4) {
        int   s0 = g_col[j],     s1 = g_col[j + 1];
        int   s2 = g_col[j + 2], s3 = g_col[j + 3];
        float w0 = g_wt[j],      w1 = g_wt[j + 1];
        float w2 = g_wt[j + 2],  w3 = g_wt[j + 3];
        uint2 u0 = ((const uint2*)(vinH + (size_t)s0 * 128))[lane];
        uint2 u1 = ((const uint2*)(vinH + (size_t)s1 * 128))[lane];
        uint2 u2 = ((const uint2*)(vinH + (size_t)s2 * 128))[lane];
        uint2 u3 = ((const uint2*)(vinH + (size_t)s3 * 128))[lane];
        float2 a0 = __half22float2(*reinterpret_cast<__half2*>(&u0.x));
        float2 b0 = __half22float2(*reinterpret_cast<__half2*>(&u0.y));
        float2 a1 = __half22float2(*reinterpret_cast<__half2*>(&u1.x));
        float2 b1 = __half22float2(*reinterpret_cast<__half2*>(&u1.y));
        float2 a2 = __half22float2(*reinterpret_cast<__half2*>(&u2.x));
        float2 b2 = __half22float2(*reinterpret_cast<__half2*>(&u2.y));
        float2 a3 = __half22float2(*reinterpret_cast<__half2*>(&u3.x));
        float2 b3 = __half22float2(*reinterpret_cast<__half2*>(&u3.y));
        ax += w0 * a0.x + w1 * a1.x + w2 * a2.x + w3 * a3.x;
        ay += w0 * a0.y + w1 * a1.y + w2 * a2.y + w3 * a3.y;
        az += w0 * b0.x + w1 * b1.x + w2 * b2.x + w3 * b3.x;
        aw += w0 * b0.y + w1 * b1.y + w2 * b2.y + w3 * b3.y;
    }
    for (; j < end; ++j) {
        int   s0 = g_col[j];
        float w0 = g_wt[j];
        uint2 u0 = ((const uint2*)(vinH + (size_t)s0 * 128))[lane];
        float2 a0 = __half22float2(*reinterpret_cast<__half2*>(&u0.x));
        float2 b0 = __half22float2(*reinterpret_cast<__half2*>(&u0.y));
        ax += w0 * a0.x; ay += w0 * a0.y; az += w0 * b0.x; aw += w0 * b0.y;
    }
}

// ---------------- SpMV: fp16 gather, fp32 accumulate ----------------
// shadow: 1 -> also write fp16 copy of result
__global__ void k_spmv(const __half* __restrict__ vinH,
                       const float* __restrict__ prev,
                       float* __restrict__ vout, __half* __restrict__ voutH,
                       int cheb, int shadow) {
    int w    = (blockIdx.x * blockDim.x + threadIdx.x) >> 5;
    int lane = threadIdx.x & 31;
    if (w >= N_NODES) return;
    float ax = 0.f, ay = 0.f, az = 0.f, aw = 0.f;
    gather_row(vinH, g_rp[w], g_rp[w + 1], lane, ax, ay, az, aw);
    float4 r;
    if (cheb) {
        float4 p = ((const float4*)prev)[w * 32 + lane];
        r.x = 2.0f * ax - p.x;
        r.y = 2.0f * ay - p.y;
        r.z = 2.0f * az - p.z;
        r.w = 2.0f * aw - p.w;
    } else {
        r.x = ax; r.y = ay; r.z = az; r.w = aw;
    }
    ((float4*)vout)[w * 32 + lane] = r;
    if (shadow) {
        __half2 h0 = __floats2half2_rn(r.x, r.y);
        __half2 h1 = __floats2half2_rn(r.z, r.w);
        uint2 hu;
        hu.x = *reinterpret_cast<uint32_t*>(&h0);
        hu.y = *reinterpret_cast<uint32_t*>(&h1);
        ((uint2*)voutH)[w * 32 + lane] = hu;
    }
}

// ---------------- final SpMV fused with head ----------------
// T4 = 2*L*T3 - T2 computed in regs; out[w] = sum_k T_k[w,:].C2[k] + c0
__global__ void k_spmv_out(const __half* __restrict__ T3h,
                           const float* __restrict__ T2,   // = prev
                           const float* __restrict__ H2,
                           const float* __restrict__ T1,
                           const float* __restrict__ T3,
                           float* __restrict__ out) {
    __shared__ float c2[5 * 128];
    for (int i = threadIdx.x; i < 5 * 128; i += blockDim.x) c2[i] = g_C2[i];
    __syncthreads();
    int w    = (blockIdx.x * blockDim.x + threadIdx.x) >> 5;
    int lane = threadIdx.x & 31;
    if (w >= N_NODES) return;

    float ax = 0.f, ay = 0.f, az = 0.f, aw = 0.f;
    gather_row(T3h, g_rp[w], g_rp[w + 1], lane, ax, ay, az, aw);

    float4 p  = ((const float4*)T2)[w * 32 + lane];
    float4 t4;
    t4.x = 2.0f * ax - p.x;
    t4.y = 2.0f * ay - p.y;
    t4.z = 2.0f * az - p.z;
    t4.w = 2.0f * aw - p.w;

    const int c = lane * 4;
    float s;
    {
        const float* w4 = c2 + 4 * 128 + c;
        s = t4.x * w4[0] + t4.y * w4[1] + t4.z * w4[2] + t4.w * w4[3];
    }
    {
        float4 h = ((const float4*)H2)[w * 32 + lane];
        const float* w0 = c2 + 0 * 128 + c;
        s += h.x * w0[0] + h.y * w0[1] + h.z * w0[2] + h.w * w0[3];
    }
    {
        float4 h = ((const float4*)T1)[w * 32 + lane];
        const float* w1 = c2 + 1 * 128 + c;
        s += h.x * w1[0] + h.y * w1[1] + h.z * w1[2] + h.w * w1[3];
    }
    {
        const float* w2 = c2 + 2 * 128 + c;
        s += p.x * w2[0] + p.y * w2[1] + p.z * w2[2] + p.w * w2[3];
    }
    {
        float4 h = ((const float4*)T3)[w * 32 + lane];
        const float* w3 = c2 + 3 * 128 + c;
        s += h.x * w3[0] + h.y * w3[1] + h.z * w3[2] + h.w * w3[3];
    }
    #pragma unroll
    for (int off = 16; off > 0; off >>= 1) s += __shfl_xor_sync(0xFFFFFFFFu, s, off);
    if (lane == 0) out[w] = s + g_c0[0];
}

// ---------------- tensor-core fused 5-slice GEMM (mma.sync, fp16 split) --
struct A5 { const float* p[5]; };

__device__ __forceinline__ void mma16816(float* d, const uint32_t* a, const uint32_t* b) {
    asm volatile(
        "mma.sync.aligned.m16n8k16.row.col.f32.f16.f16.f32 "
        "{%0,%1,%2,%3}, {%4,%5,%6,%7}, {%8,%9}, {%0,%1,%2,%3};"
        : "+f"(d[0]), "+f"(d[1]), "+f"(d[2]), "+f"(d[3])
        : "r"(a[0]), "r"(a[1]), "r"(a[2]), "r"(a[3]), "r"(b[0]), "r"(b[1]));
}

template <bool RELU>
__global__ __launch_bounds__(256, 2)
void k_gemm_mma(A5 A, const __half* __restrict__ Bh, const __half* __restrict__ Bl,
                const float* __restrict__ bias, float* __restrict__ C,
                __half* __restrict__ Ch) {
    __shared__ __align__(16) __half sAh[128 * AP];
    __shared__ __align__(16) __half sAl[128 * AP];
    __shared__ __align__(16) __half sBh[128 * AP];
    __shared__ __align__(16) __half sBl[128 * AP];

    const int tid  = threadIdx.x;
    const int wid  = tid >> 5, lane = tid & 31;
    const int g    = lane >> 2, t = lane & 3;
    const int wm   = wid & 3;
    const int wn   = wid >> 2;
    const int m0   = blockIdx.x * 128;

    float acc[2][8][4];
    #pragma unroll
    for (int mt = 0; mt < 2; ++mt)
        #pragma unroll
        for (int nt = 0; nt < 8; ++nt)
            #pragma unroll
            for (int q = 0; q < 4; ++q) acc[mt][nt][q] = 0.f;

    const int r  = tid >> 1;
    const int hf = tid & 1;

    #pragma unroll 1
    for (int c = 0; c < 20; ++c) {
        const int s  = c >> 2;
        const int k0 = (c & 3) * 32;
        __syncthreads();

        // ---- stage A (fp32 -> hi/lo fp16) ----
        {
            float f[16];
            const int gm = m0 + r;
            if (gm < N_NODES) {
                const float4* src = (const float4*)(A.p[s] + (size_t)gm * 128 + k0 + hf * 16);
                #pragma unroll
                for (int i = 0; i < 4; ++i) *(float4*)&f[i * 4] = src[i];
            } else {
                #pragma unroll
                for (int i = 0; i < 16; ++i) f[i] = 0.f;
            }
            uint32_t hb[8], lb[8];
            #pragma unroll
            for (int i = 0; i < 8; ++i) {
                __half2 h2 = __floats2half2_rn(f[2 * i], f[2 * i + 1]);
                float2  hc = __half22float2(h2);
                __half2 l2 = __floats2half2_rn(f[2 * i] - hc.x, f[2 * i + 1] - hc.y);
                hb[i] = *reinterpret_cast<uint32_t*>(&h2);
                lb[i] = *reinterpret_cast<uint32_t*>(&l2);
            }
            const int o = r * AP + hf * 16;
            *(uint4*)&sAh[o]     = *(uint4*)&hb[0];
            *(uint4*)&sAh[o + 8] = *(uint4*)&hb[4];
            *(uint4*)&sAl[o]     = *(uint4*)&lb[0];
            *(uint4*)&sAl[o + 8] = *(uint4*)&lb[4];
        }
        // ---- stage B (pre-split fp16 [s][n][k]) ----
        {
            const size_t gb = (size_t)s * 16384 + (size_t)r * 128 + k0 + hf * 16;
            const uint4* sh = (const uint4*)(Bh + gb);
            const uint4* sl = (const uint4*)(Bl + gb);
            const int o = r * AP + hf * 16;
            *(uint4*)&sBh[o]     = sh[0];
            *(uint4*)&sBh[o + 8] = sh[1];
            *(uint4*)&sBl[o]     = sl[0];
            *(uint4*)&sBl[o + 8] = sl[1];
        }
        __syncthreads();

        // ---- compute: 2 k-steps of 16, products hh + lh + hl ----
        #pragma unroll
        for (int ks = 0; ks < 2; ++ks) {
            const int kb = ks * 16 + 2 * t;
            uint32_t bf[8][2], ah[2][4], al[2][4];
            #pragma unroll
            for (int nt = 0; nt < 8; ++nt) {
                const int nb = (wn * 64 + nt * 8 + g) * AP + kb;
                bf[nt][0] = *(const uint32_t*)&sBh[nb];
                bf[nt][1] = *(const uint32_t*)&sBh[nb + 8];
            }
            #pragma unroll
            for (int mt = 0; mt < 2; ++mt) {
                const int rb = (wm * 32 + mt * 16 + g) * AP + kb;
                ah[mt][0] = *(const uint32_t*)&sAh[rb];
                ah[mt][1] = *(const uint32_t*)&sAh[rb + 8 * AP];
                ah[mt][2] = *(const uint32_t*)&sAh[rb + 8];
                ah[mt][3] = *(const uint32_t*)&sAh[rb + 8 * AP + 8];
                al[mt][0] = *(const uint32_t*)&sAl[rb];
                al[mt][1] = *(const uint32_t*)&sAl[rb + 8 * AP];
                al[mt][2] = *(const uint32_t*)&sAl[rb + 8];
                al[mt][3] = *(const uint32_t*)&sAl[rb + 8 * AP + 8];
            }
            #pragma unroll
            for (int mt = 0; mt < 2; ++mt)
                #pragma unroll
                for (int nt = 0; nt < 8; ++nt) mma16816(acc[mt][nt], ah[mt], bf[nt]);
            #pragma unroll
            for (int mt = 0; mt < 2; ++mt)
                #pragma unroll
                for (int nt = 0; nt < 8; ++nt) mma16816(acc[mt][nt], al[mt], bf[nt]);
            #pragma unroll
            for (int nt = 0; nt < 8; ++nt) {
                const int nb = (wn * 64 + nt * 8 + g) * AP + kb;
                bf[nt][0] = *(const uint32_t*)&sBl[nb];
                bf[nt][1] = *(const uint32_t*)&sBl[nb + 8];
            }
            #pragma unroll
            for (int mt = 0; mt < 2; ++mt)
                #pragma unroll
                for (int nt = 0; nt < 8; ++nt) mma16816(acc[mt][nt], ah[mt], bf[nt]);
        }
    }

    // ---- epilogue: bias (+relu), fp32 + fp16 shadow ----
    #pragma unroll
    for (int mt = 0; mt < 2; ++mt) {
        #pragma unroll
        for (int half = 0; half < 2; ++half) {
            const int row = m0 + wm * 32 + mt * 16 + g + half * 8;
            if (row < N_NODES) {
                #pragma unroll
                for (int nt = 0; nt < 8; ++nt) {
                    const int col = wn * 64 + nt * 8 + 2 * t;
                    float v0 = acc[mt][nt][half * 2 + 0] + __ldg(bias + col);
                    float v1 = acc[mt][nt][half * 2 + 1] + __ldg(bias + col + 1);
                    if (RELU) { v0 = fmaxf(v0, 0.f); v1 = fmaxf(v1, 0.f); }
                    float2 o; o.x = v0; o.y = v1;
                    *(float2*)(C + (size_t)row * 128 + col) = o;
                    __half2 h2 = __floats2half2_rn(v0, v1);
                    *(uint32_t*)(Ch + (size_t)row * 128 + col) =
                        *reinterpret_cast<uint32_t*>(&h2);
                }
            }
        }
    }
}

// ---------------- launch --------------------------------------------------
extern "C" void kernel_launch(void* const* d_in, const int* in_sizes, int n_in,
                              void* d_out, int out_size) {
    const float* x  = (const float*)d_in[0];
    const int*   ei = (const int*)  d_in[1];
    const float* W0 = (const float*)d_in[2];
    const float* b0 = (const float*)d_in[3];
    const float* W1 = (const float*)d_in[4];
    const float* b1 = (const float*)d_in[5];
    const float* W2 = (const float*)d_in[6];
    const float* b2 = (const float*)d_in[7];
    const float* Wl = (const float*)d_in[8];
    const float* bl = (const float*)d_in[9];
    float* out = (float*)d_out;

    float *T1, *T2, *T3, *T4, *H, *H2;
    __half *Xh, *T1h, *T2h, *T3h, *Hh, *H2h;
    __half *W0th, *W0tl, *W1th, *W1tl;
    cudaGetSymbolAddress((void**)&T1,   g_T1);
    cudaGetSymbolAddress((void**)&T2,   g_T2);
    cudaGetSymbolAddress((void**)&T3,   g_T3);
    cudaGetSymbolAddress((void**)&T4,   g_T4);
    cudaGetSymbolAddress((void**)&H,    g_H);
    cudaGetSymbolAddress((void**)&H2,   g_H2);
    cudaGetSymbolAddress((void**)&Xh,   g_Xh);
    cudaGetSymbolAddress((void**)&T1h,  g_T1h);
    cudaGetSymbolAddress((void**)&T2h,  g_T2h);
    cudaGetSymbolAddress((void**)&T3h,  g_T3h);
    cudaGetSymbolAddress((void**)&Hh,   g_Hh);
    cudaGetSymbolAddress((void**)&H2h,  g_H2h);
    cudaGetSymbolAddress((void**)&W0th, g_W0th);
    cudaGetSymbolAddress((void**)&W0tl, g_W0tl);
    cudaGetSymbolAddress((void**)&W1th, g_W1th);
    cudaGetSymbolAddress((void**)&W1tl, g_W1tl);

    const int nb_n = (N_NODES + 255) / 256;
    const int nb_e = (N_EDGES + 255) / 256;
    const int spmv_blocks = (N_NODES * 32 + 255) / 256;
    const int gemm_blocks = (N_NODES + 127) / 128;
    const int conv_blocks = (N_NODES * 32 + 255) / 256;
    const int wsp_blocks  = (5 * 128 * 128 + 255) / 256;

    k_zero  <<<nb_n, 256>>>();
    k_count <<<nb_e, 256>>>(ei);
    k_dinv  <<<nb_n, 256>>>();
    k_scanA <<<SCAN_B, 1024>>>();
    k_scanB <<<1, 1>>>();
    k_scanC <<<SCAN_B, 1024>>>();
    k_fill  <<<nb_e, 256>>>(ei);
    k_fold  <<<5, 128>>>(W2, b2, Wl, bl);
    k_wsplit<<<wsp_blocks, 256>>>(W0, W0th, W0tl);
    k_wsplit<<<wsp_blocks, 256>>>(W1, W1th, W1tl);
    k_h16   <<<conv_blocks, 256>>>(x, Xh);

    // ---- layer 0 (T0 = x) ----
    k_spmv<<<spmv_blocks, 256>>>(Xh,  nullptr, T1, T1h, 0, 1);
    k_spmv<<<spmv_blocks, 256>>>(T1h, x,       T2, T2h, 1, 1);
    k_spmv<<<spmv_blocks, 256>>>(T2h, T1,      T3, T3h, 1, 1);
    k_spmv<<<spmv_blocks, 256>>>(T3h, T2,      T4, nullptr, 1, 0);
    { A5 a; a.p[0]=x; a.p[1]=T1; a.p[2]=T2; a.p[3]=T3; a.p[4]=T4;
      k_gemm_mma<true><<<gemm_blocks, 256>>>(a, W0th, W0tl, b0, H, Hh); }

    // ---- layer 1 (T0 = H) ----
    k_spmv<<<spmv_blocks, 256>>>(Hh,  nullptr, T1, T1h, 0, 1);
    k_spmv<<<spmv_blocks, 256>>>(T1h, H,       T2, T2h, 1, 1);
    k_spmv<<<spmv_blocks, 256>>>(T2h, T1,      T3, T3h, 1, 1);
    k_spmv<<<spmv_blocks, 256>>>(T3h, T2,      T4, nullptr, 1, 0);
    { A5 a; a.p[0]=H; a.p[1]=T1; a.p[2]=T2; a.p[3]=T3; a.p[4]=T4;
      k_gemm_mma<true><<<gemm_blocks, 256>>>(a, W1th, W1tl, b1, H2, H2h); }

    // ---- layer 2 (T0 = H2): 3 SpMVs, then final SpMV fused with head ----
    k_spmv<<<spmv_blocks, 256>>>(H2h, nullptr, T1, T1h, 0, 1);
    k_spmv<<<spmv_blocks, 256>>>(T1h, H2,      T2, T2h, 1, 1);
    k_spmv<<<spmv_blocks, 256>>>(T2h, T1,      T3, T3h, 1, 1);
    k_spmv_out<<<spmv_blocks, 256>>>(T3h, T2, H2, T1, T3, out);
}

// round 10
// speedup vs baseline: 2.7634x; 1.0931x over previous
#include <cuda_runtime.h>
#include <cuda_fp16.h>
#include <cstdint>
#include <math.h>

#define N_NODES 50000
#define N_EDGES 800000
#define FDIM    128
#define SCAN_B  ((N_NODES + 1023) / 1024)
#define AP      40                  // padded halves per smem row (80B)
#define SMEM_BYTES (4 * 2 * 128 * AP * 2)   // 4 arrays x 2 bufs x 128 rows x AP halves

// ---------------- static device scratch ----------------
__device__ int    g_deg[N_NODES];
__device__ int    g_cnt[N_NODES];
__device__ int    g_ofs[N_NODES];
__device__ int    g_rp[N_NODES + 1];
__device__ float  g_dinv[N_NODES];
__device__ int    g_col[N_EDGES];
__device__ float  g_wt[N_EDGES];
__device__ int    g_bsum[SCAN_B];
__device__ int    g_bofs[SCAN_B];
__device__ float  g_T1[N_NODES * FDIM];
__device__ float  g_T2[N_NODES * FDIM];
__device__ float  g_T3[N_NODES * FDIM];
__device__ float  g_H [N_NODES * FDIM];
__device__ float  g_H2[N_NODES * FDIM];
__device__ __half g_Xh [N_NODES * FDIM];
__device__ __half g_Xl [N_NODES * FDIM];
__device__ __half g_T1h[N_NODES * FDIM];
__device__ __half g_T1l[N_NODES * FDIM];
__device__ __half g_T2h[N_NODES * FDIM];
__device__ __half g_T2l[N_NODES * FDIM];
__device__ __half g_T3h[N_NODES * FDIM];
__device__ __half g_T3l[N_NODES * FDIM];
__device__ __half g_T4h[N_NODES * FDIM];
__device__ __half g_T4l[N_NODES * FDIM];
__device__ __half g_Hh [N_NODES * FDIM];
__device__ __half g_Hl [N_NODES * FDIM];
__device__ __half g_H2h[N_NODES * FDIM];
__device__ __half g_W0th[5 * 128 * 128];   // W transposed [s][n][k], hi
__device__ __half g_W0tl[5 * 128 * 128];   // lo
__device__ __half g_W1th[5 * 128 * 128];
__device__ __half g_W1tl[5 * 128 * 128];
__device__ float  g_C2[5 * FDIM];
__device__ float  g_c0[1];

// ---------------- preprocessing ----------------
__global__ void k_zero() {
    int i = blockIdx.x * blockDim.x + threadIdx.x;
    if (i < N_NODES) { g_deg[i] = 0; g_cnt[i] = 0; }
}

__global__ void k_count(const int* __restrict__ ei) {
    int e = blockIdx.x * blockDim.x + threadIdx.x;
    if (e < N_EDGES) {
        int s = ei[e], d = ei[N_EDGES + e];
        if (s != d) {
            atomicAdd(&g_deg[s], 1);
            atomicAdd(&g_cnt[d], 1);
        }
    }
}

__global__ void k_dinv() {
    int i = blockIdx.x * blockDim.x + threadIdx.x;
    if (i < N_NODES) {
        int dg = g_deg[i];
        g_dinv[i] = (dg > 0) ? rsqrtf((float)dg) : 0.0f;
    }
}

__global__ void k_scanA() {
    __shared__ int wsum[32];
    int tid  = threadIdx.x;
    int lane = tid & 31, wid = tid >> 5;
    int i = blockIdx.x * 1024 + tid;
    int v = (i < N_NODES) ? g_cnt[i] : 0;
    int x = v;
    #pragma unroll
    for (int off = 1; off < 32; off <<= 1) {
        int y = __shfl_up_sync(0xFFFFFFFFu, x, off);
        if (lane >= off) x += y;
    }
    if (lane == 31) wsum[wid] = x;
    __syncthreads();
    if (wid == 0) {
        int y = wsum[lane];
        #pragma unroll
        for (int off = 1; off < 32; off <<= 1) {
            int z = __shfl_up_sync(0xFFFFFFFFu, y, off);
            if (lane >= off) y += z;
        }
        wsum[lane] = y;
    }
    __syncthreads();
    int excl = x - v + (wid > 0 ? wsum[wid - 1] : 0);
    if (i < N_NODES) g_rp[i] = excl;
    if (tid == 0) g_bsum[blockIdx.x] = wsum[31];
}

__global__ void k_scanB() {
    int run = 0;
    for (int b = 0; b < SCAN_B; ++b) {
        g_bofs[b] = run;
        run += g_bsum[b];
    }
    g_rp[N_NODES] = run;
}

__global__ void k_scanC() {
    int i = blockIdx.x * 1024 + threadIdx.x;
    if (i < N_NODES) {
        int r = g_rp[i] + g_bofs[blockIdx.x];
        g_rp[i]  = r;
        g_ofs[i] = r;
    }
}

__global__ void k_fill(const int* __restrict__ ei) {
    int e = blockIdx.x * blockDim.x + threadIdx.x;
    if (e < N_EDGES) {
        int s = ei[e], d = ei[N_EDGES + e];
        if (s != d) {
            int p = atomicAdd(&g_ofs[d], 1);
            g_col[p] = s;
            g_wt[p]  = -g_dinv[s] * g_dinv[d];
        }
    }
}

__global__ void k_fold(const float* __restrict__ W2, const float* __restrict__ b2,
                       const float* __restrict__ Wl, const float* __restrict__ bl) {
    int k = blockIdx.x;
    int f = threadIdx.x;
    const float* row = W2 + ((size_t)k * 128 + f) * 128;
    float s = 0.f;
    #pragma unroll 4
    for (int w = 0; w < 128; ++w) s += row[w] * Wl[w];
    g_C2[k * 128 + f] = s;
    if (k == 0 && f == 0) {
        float c = bl[0];
        for (int w = 0; w < 128; ++w) c += b2[w] * Wl[w];
        g_c0[0] = c;
    }
}

// split W [5][k=128][n=128] fp32 -> transposed [5][n][k] fp16 hi/lo
__global__ void k_wsplit(const float* __restrict__ W,
                         __half* __restrict__ Wh, __half* __restrict__ Wl) {
    int o = blockIdx.x * 256 + threadIdx.x;
    if (o < 5 * 128 * 128) {
        int s = o >> 14, r = o & 16383, n = r >> 7, k = r & 127;
        float w = W[s * 16384 + k * 128 + n];
        __half h = __float2half_rn(w);
        Wh[o] = h;
        Wl[o] = __float2half_rn(w - __half2float(h));
    }
}

// fp32 -> fp16 hi + lo shadows (for x)
__global__ void k_h16(const float* __restrict__ src,
                      __half* __restrict__ dh, __half* __restrict__ dl) {
    int i = blockIdx.x * blockDim.x + threadIdx.x;
    if (i < N_NODES * 32) {
        float4 v = ((const float4*)src)[i];
        __half2 a = __floats2half2_rn(v.x, v.y);
        __half2 b = __floats2half2_rn(v.z, v.w);
        float2 fa = __half22float2(a), fb = __half22float2(b);
        __half2 la = __floats2half2_rn(v.x - fa.x, v.y - fa.y);
        __half2 lb = __floats2half2_rn(v.z - fb.x, v.w - fb.y);
        uint2 u, ul;
        u.x  = *reinterpret_cast<uint32_t*>(&a);
        u.y  = *reinterpret_cast<uint32_t*>(&b);
        ul.x = *reinterpret_cast<uint32_t*>(&la);
        ul.y = *reinterpret_cast<uint32_t*>(&lb);
        ((uint2*)dh)[i] = u;
        ((uint2*)dl)[i] = ul;
    }
}

// ---------------- gather core ----------------
__device__ __forceinline__ void gather_row(
    const __half* __restrict__ vinH, int beg, int end, int lane,
    float& ax, float& ay, float& az, float& aw)
{
    int j = beg;
    for (; j + 3 < end; j += 4) {
        int   s0 = g_col[j],     s1 = g_col[j + 1];
        int   s2 = g_col[j + 2], s3 = g_col[j + 3];
        float w0 = g_wt[j],      w1 = g_wt[j + 1];
        float w2 = g_wt[j + 2],  w3 = g_wt[j + 3];
        uint2 u0 = ((const uint2*)(vinH + (size_t)s0 * 128))[lane];
        uint2 u1 = ((const uint2*)(vinH + (size_t)s1 * 128))[lane];
        uint2 u2 = ((const uint2*)(vinH + (size_t)s2 * 128))[lane];
        uint2 u3 = ((const uint2*)(vinH + (size_t)s3 * 128))[lane];
        float2 a0 = __half22float2(*reinterpret_cast<__half2*>(&u0.x));
        float2 b0 = __half22float2(*reinterpret_cast<__half2*>(&u0.y));
        float2 a1 = __half22float2(*reinterpret_cast<__half2*>(&u1.x));
        float2 b1 = __half22float2(*reinterpret_cast<__half2*>(&u1.y));
        float2 a2 = __half22float2(*reinterpret_cast<__half2*>(&u2.x));
        float2 b2 = __half22float2(*reinterpret_cast<__half2*>(&u2.y));
        float2 a3 = __half22float2(*reinterpret_cast<__half2*>(&u3.x));
        float2 b3 = __half22float2(*reinterpret_cast<__half2*>(&u3.y));
        ax += w0 * a0.x + w1 * a1.x + w2 * a2.x + w3 * a3.x;
        ay += w0 * a0.y + w1 * a1.y + w2 * a2.y + w3 * a3.y;
        az += w0 * b0.x + w1 * b1.x + w2 * b2.x + w3 * b3.x;
        aw += w0 * b0.y + w1 * b1.y + w2 * b2.y + w3 * b3.y;
    }
    for (; j < end; ++j) {
        int   s0 = g_col[j];
        float w0 = g_wt[j];
        uint2 u0 = ((const uint2*)(vinH + (size_t)s0 * 128))[lane];
        float2 a0 = __half22float2(*reinterpret_cast<__half2*>(&u0.x));
        float2 b0 = __half22float2(*reinterpret_cast<__half2*>(&u0.y));
        ax += w0 * a0.x; ay += w0 * a0.y; az += w0 * b0.x; aw += w0 * b0.y;
    }
}

// ---------------- SpMV: fp16 gather, fp32 accumulate ----------------
// vout (fp32) optional; voutH (hi) always; voutL (lo) optional
__global__ void k_spmv(const __half* __restrict__ vinH,
                       const float* __restrict__ prev,
                       float* __restrict__ vout,
                       __half* __restrict__ voutH,
                       __half* __restrict__ voutL,
                       int cheb) {
    int w    = (blockIdx.x * blockDim.x + threadIdx.x) >> 5;
    int lane = threadIdx.x & 31;
    if (w >= N_NODES) return;
    float ax = 0.f, ay = 0.f, az = 0.f, aw = 0.f;
    gather_row(vinH, g_rp[w], g_rp[w + 1], lane, ax, ay, az, aw);
    float4 r;
    if (cheb) {
        float4 p = ((const float4*)prev)[w * 32 + lane];
        r.x = 2.0f * ax - p.x;
        r.y = 2.0f * ay - p.y;
        r.z = 2.0f * az - p.z;
        r.w = 2.0f * aw - p.w;
    } else {
        r.x = ax; r.y = ay; r.z = az; r.w = aw;
    }
    if (vout) ((float4*)vout)[w * 32 + lane] = r;
    __half2 h0 = __floats2half2_rn(r.x, r.y);
    __half2 h1 = __floats2half2_rn(r.z, r.w);
    uint2 hu;
    hu.x = *reinterpret_cast<uint32_t*>(&h0);
    hu.y = *reinterpret_cast<uint32_t*>(&h1);
    ((uint2*)voutH)[w * 32 + lane] = hu;
    if (voutL) {
        float2 f0 = __half22float2(h0), f1 = __half22float2(h1);
        __half2 l0 = __floats2half2_rn(r.x - f0.x, r.y - f0.y);
        __half2 l1 = __floats2half2_rn(r.z - f1.x, r.w - f1.y);
        uint2 lu;
        lu.x = *reinterpret_cast<uint32_t*>(&l0);
        lu.y = *reinterpret_cast<uint32_t*>(&l1);
        ((uint2*)voutL)[w * 32 + lane] = lu;
    }
}

// ---------------- final SpMV fused with head ----------------
__global__ void k_spmv_out(const __half* __restrict__ T3h,
                           const float* __restrict__ T2,   // = prev
                           const float* __restrict__ H2,
                           const float* __restrict__ T1,
                           const float* __restrict__ T3,
                           float* __restrict__ out) {
    __shared__ float c2[5 * 128];
    for (int i = threadIdx.x; i < 5 * 128; i += blockDim.x) c2[i] = g_C2[i];
    __syncthreads();
    int w    = (blockIdx.x * blockDim.x + threadIdx.x) >> 5;
    int lane = threadIdx.x & 31;
    if (w >= N_NODES) return;

    float ax = 0.f, ay = 0.f, az = 0.f, aw = 0.f;
    gather_row(T3h, g_rp[w], g_rp[w + 1], lane, ax, ay, az, aw);

    float4 p  = ((const float4*)T2)[w * 32 + lane];
    float4 t4;
    t4.x = 2.0f * ax - p.x;
    t4.y = 2.0f * ay - p.y;
    t4.z = 2.0f * az - p.z;
    t4.w = 2.0f * aw - p.w;

    const int c = lane * 4;
    float s;
    {
        const float* w4 = c2 + 4 * 128 + c;
        s = t4.x * w4[0] + t4.y * w4[1] + t4.z * w4[2] + t4.w * w4[3];
    }
    {
        float4 h = ((const float4*)H2)[w * 32 + lane];
        const float* w0 = c2 + 0 * 128 + c;
        s += h.x * w0[0] + h.y * w0[1] + h.z * w0[2] + h.w * w0[3];
    }
    {
        float4 h = ((const float4*)T1)[w * 32 + lane];
        const float* w1 = c2 + 1 * 128 + c;
        s += h.x * w1[0] + h.y * w1[1] + h.z * w1[2] + h.w * w1[3];
    }
    {
        const float* w2 = c2 + 2 * 128 + c;
        s += p.x * w2[0] + p.y * w2[1] + p.z * w2[2] + p.w * w2[3];
    }
    {
        float4 h = ((const float4*)T3)[w * 32 + lane];
        const float* w3 = c2 + 3 * 128 + c;
        s += h.x * w3[0] + h.y * w3[1] + h.z * w3[2] + h.w * w3[3];
    }
    #pragma unroll
    for (int off = 16; off > 0; off >>= 1) s += __shfl_xor_sync(0xFFFFFFFFu, s, off);
    if (lane == 0) out[w] = s + g_c0[0];
}

// ---------------- tensor-core GEMM: cp.async double-buffered ----------
struct P5 { const __half* h[5]; const __half* l[5]; };

__device__ __forceinline__ void mma16816(float* d, const uint32_t* a, const uint32_t* b) {
    asm volatile(
        "mma.sync.aligned.m16n8k16.row.col.f32.f16.f16.f32 "
        "{%0,%1,%2,%3}, {%4,%5,%6,%7}, {%8,%9}, {%0,%1,%2,%3};"
        : "+f"(d[0]), "+f"(d[1]), "+f"(d[2]), "+f"(d[3])
        : "r"(a[0]), "r"(a[1]), "r"(a[2]), "r"(a[3]), "r"(b[0]), "r"(b[1]));
}

__device__ __forceinline__ void cpa16(uint32_t dst, const void* src, int srcsize) {
    asm volatile("cp.async.cg.shared.global [%0], [%1], 16, %2;"
                 :: "r"(dst), "l"(src), "r"(srcsize));
}

template <bool RELU, bool WLO>
__global__ __launch_bounds__(256, 2)
void k_gemm_mma(P5 A, const __half* __restrict__ Bh, const __half* __restrict__ Bl,
                const float* __restrict__ bias, float* __restrict__ C,
                __half* __restrict__ Ch, __half* __restrict__ Cl) {
    extern __shared__ __align__(16) __half sm[];
    // layout: [buf][arr] arr: 0=Ah 1=Al 2=Bh 3=Bl, each 128*AP halves
    const int ARR = 128 * AP;

    const int tid  = threadIdx.x;
    const int wid  = tid >> 5, lane = tid & 31;
    const int g    = lane >> 2, t = lane & 3;
    const int wm   = wid & 3;
    const int wn   = wid >> 2;
    const int m0   = blockIdx.x * 128;

    uint32_t smBase;
    asm("{ .reg .u64 tt; cvta.to.shared.u64 tt, %1; cvt.u32.u64 %0, tt; }"
        : "=r"(smBase) : "l"(sm));

    float acc[2][8][4];
    #pragma unroll
    for (int mt = 0; mt < 2; ++mt)
        #pragma unroll
        for (int nt = 0; nt < 8; ++nt)
            #pragma unroll
            for (int q = 0; q < 4; ++q) acc[mt][nt][q] = 0.f;

    // ---- staging: 8 cp.asyncs per thread per chunk ----
    auto do_stage = [&](int c, int buf) {
        const int s = c >> 2, k0 = (c & 3) * 32;
        const __half* Ah = A.h[s];
        const __half* Al = A.l[s];
        const size_t bofs = (size_t)s * 16384 + k0;
        const uint32_t base = smBase + (uint32_t)(buf * 4 * ARR) * 2;
        #pragma unroll
        for (int i = 0; i < 2; ++i) {
            int q = tid + i * 256;
            int row = q >> 2, seg = q & 3;
            int gm = m0 + row;
            int ok  = (gm < N_NODES) ? 16 : 0;
            int gmc = (gm < N_NODES) ? gm : 0;
            uint32_t so = (uint32_t)((row * AP + seg * 8) * 2);
            cpa16(base + 0 * ARR * 2 + so, Ah + (size_t)gmc * 128 + k0 + seg * 8, ok);
            cpa16(base + 1 * ARR * 2 + so, Al + (size_t)gmc * 128 + k0 + seg * 8, ok);
            cpa16(base + 2 * ARR * 2 + so, Bh + bofs + (size_t)row * 128 + seg * 8, 16);
            cpa16(base + 3 * ARR * 2 + so, Bl + bofs + (size_t)row * 128 + seg * 8, 16);
        }
    };

    do_stage(0, 0);
    asm volatile("cp.async.commit_group;" ::: "memory");

    #pragma unroll 1
    for (int c = 0; c < 20; ++c) {
        const int cur = c & 1;
        if (c + 1 < 20) {
            do_stage(c + 1, cur ^ 1);
            asm volatile("cp.async.commit_group;" ::: "memory");
            asm volatile("cp.async.wait_group 1;" ::: "memory");
        } else {
            asm volatile("cp.async.wait_group 0;" ::: "memory");
        }
        __syncthreads();

        const __half* pAh = sm + (cur * 4 + 0) * ARR;
        const __half* pAl = sm + (cur * 4 + 1) * ARR;
        const __half* pBh = sm + (cur * 4 + 2) * ARR;
        const __half* pBl = sm + (cur * 4 + 3) * ARR;

        #pragma unroll
        for (int ks = 0; ks < 2; ++ks) {
            const int kb = ks * 16 + 2 * t;
            uint32_t bf[8][2], ah[2][4], al[2][4];
            #pragma unroll
            for (int nt = 0; nt < 8; ++nt) {
                const int nb = (wn * 64 + nt * 8 + g) * AP + kb;
                bf[nt][0] = *(const uint32_t*)&pBh[nb];
                bf[nt][1] = *(const uint32_t*)&pBh[nb + 8];
            }
            #pragma unroll
            for (int mt = 0; mt < 2; ++mt) {
                const int rb = (wm * 32 + mt * 16 + g) * AP + kb;
                ah[mt][0] = *(const uint32_t*)&pAh[rb];
                ah[mt][1] = *(const uint32_t*)&pAh[rb + 8 * AP];
                ah[mt][2] = *(const uint32_t*)&pAh[rb + 8];
                ah[mt][3] = *(const uint32_t*)&pAh[rb + 8 * AP + 8];
                al[mt][0] = *(const uint32_t*)&pAl[rb];
                al[mt][1] = *(const uint32_t*)&pAl[rb + 8 * AP];
                al[mt][2] = *(const uint32_t*)&pAl[rb + 8];
                al[mt][3] = *(const uint32_t*)&pAl[rb + 8 * AP + 8];
            }
            #pragma unroll
            for (int mt = 0; mt < 2; ++mt)
                #pragma unroll
                for (int nt = 0; nt < 8; ++nt) mma16816(acc[mt][nt], ah[mt], bf[nt]);
            #pragma unroll
            for (int mt = 0; mt < 2; ++mt)
                #pragma unroll
                for (int nt = 0; nt < 8; ++nt) mma16816(acc[mt][nt], al[mt], bf[nt]);
            #pragma unroll
            for (int nt = 0; nt < 8; ++nt) {
                const int nb = (wn * 64 + nt * 8 + g) * AP + kb;
                bf[nt][0] = *(const uint32_t*)&pBl[nb];
                bf[nt][1] = *(const uint32_t*)&pBl[nb + 8];
            }
            #pragma unroll
            for (int mt = 0; mt < 2; ++mt)
                #pragma unroll
                for (int nt = 0; nt < 8; ++nt) mma16816(acc[mt][nt], ah[mt], bf[nt]);
        }
        __syncthreads();
    }

    // ---- epilogue: bias (+relu), fp32 + hi shadow (+ lo shadow) ----
    #pragma unroll
    for (int mt = 0; mt < 2; ++mt) {
        #pragma unroll
        for (int half = 0; half < 2; ++half) {
            const int row = m0 + wm * 32 + mt * 16 + g + half * 8;
            if (row < N_NODES) {
                #pragma unroll
                for (int nt = 0; nt < 8; ++nt) {
                    const int col = wn * 64 + nt * 8 + 2 * t;
                    float v0 = acc[mt][nt][half * 2 + 0] + __ldg(bias + col);
                    float v1 = acc[mt][nt][half * 2 + 1] + __ldg(bias + col + 1);
                    if (RELU) { v0 = fmaxf(v0, 0.f); v1 = fmaxf(v1, 0.f); }
                    float2 o; o.x = v0; o.y = v1;
                    *(float2*)(C + (size_t)row * 128 + col) = o;
                    __half2 h2 = __floats2half2_rn(v0, v1);
                    *(uint32_t*)(Ch + (size_t)row * 128 + col) =
                        *reinterpret_cast<uint32_t*>(&h2);
                    if (WLO) {
                        float2 hf = __half22float2(h2);
                        __half2 l2 = __floats2half2_rn(v0 - hf.x, v1 - hf.y);
                        *(uint32_t*)(Cl + (size_t)row * 128 + col) =
                            *reinterpret_cast<uint32_t*>(&l2);
                    }
                }
            }
        }
    }
}

// ---------------- launch --------------------------------------------------
extern "C" void kernel_launch(void* const* d_in, const int* in_sizes, int n_in,
                              void* d_out, int out_size) {
    const float* x  = (const float*)d_in[0];
    const int*   ei = (const int*)  d_in[1];
    const float* W0 = (const float*)d_in[2];
    const float* b0 = (const float*)d_in[3];
    const float* W1 = (const float*)d_in[4];
    const float* b1 = (const float*)d_in[5];
    const float* W2 = (const float*)d_in[6];
    const float* b2 = (const float*)d_in[7];
    const float* Wl = (const float*)d_in[8];
    const float* bl = (const float*)d_in[9];
    float* out = (float*)d_out;

    float *T1, *T2, *T3, *H, *H2;
    __half *Xh, *Xl, *T1h, *T1l, *T2h, *T2l, *T3h, *T3l, *T4h, *T4l;
    __half *Hh, *Hl, *H2h;
    __half *W0th, *W0tl, *W1th, *W1tl;
    cudaGetSymbolAddress((void**)&T1,   g_T1);
    cudaGetSymbolAddress((void**)&T2,   g_T2);
    cudaGetSymbolAddress((void**)&T3,   g_T3);
    cudaGetSymbolAddress((void**)&H,    g_H);
    cudaGetSymbolAddress((void**)&H2,   g_H2);
    cudaGetSymbolAddress((void**)&Xh,   g_Xh);
    cudaGetSymbolAddress((void**)&Xl,   g_Xl);
    cudaGetSymbolAddress((void**)&T1h,  g_T1h);
    cudaGetSymbolAddress((void**)&T1l,  g_T1l);
    cudaGetSymbolAddress((void**)&T2h,  g_T2h);
    cudaGetSymbolAddress((void**)&T2l,  g_T2l);
    cudaGetSymbolAddress((void**)&T3h,  g_T3h);
    cudaGetSymbolAddress((void**)&T3l,  g_T3l);
    cudaGetSymbolAddress((void**)&T4h,  g_T4h);
    cudaGetSymbolAddress((void**)&T4l,  g_T4l);
    cudaGetSymbolAddress((void**)&Hh,   g_Hh);
    cudaGetSymbolAddress((void**)&Hl,   g_Hl);
    cudaGetSymbolAddress((void**)&H2h,  g_H2h);
    cudaGetSymbolAddress((void**)&W0th, g_W0th);
    cudaGetSymbolAddress((void**)&W0tl, g_W0tl);
    cudaGetSymbolAddress((void**)&W1th, g_W1th);
    cudaGetSymbolAddress((void**)&W1tl, g_W1tl);

    cudaFuncSetAttribute(k_gemm_mma<true, true>,
                         cudaFuncAttributeMaxDynamicSharedMemorySize, SMEM_BYTES);
    cudaFuncSetAttribute(k_gemm_mma<true, false>,
                         cudaFuncAttributeMaxDynamicSharedMemorySize, SMEM_BYTES);

    const int nb_n = (N_NODES + 255) / 256;
    const int nb_e = (N_EDGES + 255) / 256;
    const int spmv_blocks = (N_NODES * 32 + 255) / 256;
    const int gemm_blocks = (N_NODES + 127) / 128;
    const int conv_blocks = (N_NODES * 32 + 255) / 256;
    const int wsp_blocks  = (5 * 128 * 128 + 255) / 256;

    k_zero  <<<nb_n, 256>>>();
    k_count <<<nb_e, 256>>>(ei);
    k_dinv  <<<nb_n, 256>>>();
    k_scanA <<<SCAN_B, 1024>>>();
    k_scanB <<<1, 1>>>();
    k_scanC <<<SCAN_B, 1024>>>();
    k_fill  <<<nb_e, 256>>>(ei);
    k_fold  <<<5, 128>>>(W2, b2, Wl, bl);
    k_wsplit<<<wsp_blocks, 256>>>(W0, W0th, W0tl);
    k_wsplit<<<wsp_blocks, 256>>>(W1, W1th, W1tl);
    k_h16   <<<conv_blocks, 256>>>(x, Xh, Xl);

    // ---- layer 0 (T0 = x) ----
    k_spmv<<<spmv_blocks, 256>>>(Xh,  nullptr, T1, T1h, T1l, 0);
    k_spmv<<<spmv_blocks, 256>>>(T1h, x,       T2, T2h, T2l, 1);
    k_spmv<<<spmv_blocks, 256>>>(T2h, T1,      T3, T3h, T3l, 1);
    k_spmv<<<spmv_blocks, 256>>>(T3h, T2,      nullptr, T4h, T4l, 1);
    { P5 a;
      a.h[0]=Xh;  a.h[1]=T1h; a.h[2]=T2h; a.h[3]=T3h; a.h[4]=T4h;
      a.l[0]=Xl;  a.l[1]=T1l; a.l[2]=T2l; a.l[3]=T3l; a.l[4]=T4l;
      k_gemm_mma<true, true><<<gemm_blocks, 256, SMEM_BYTES>>>(
          a, W0th, W0tl, b0, H, Hh, Hl); }

    // ---- layer 1 (T0 = H) ----
    k_spmv<<<spmv_blocks, 256>>>(Hh,  nullptr, T1, T1h, T1l, 0);
    k_spmv<<<spmv_blocks, 256>>>(T1h, H,       T2, T2h, T2l, 1);
    k_spmv<<<spmv_blocks, 256>>>(T2h, T1,      T3, T3h, T3l, 1);
    k_spmv<<<spmv_blocks, 256>>>(T3h, T2,      nullptr, T4h, T4l, 1);
    { P5 a;
      a.h[0]=Hh;  a.h[1]=T1h; a.h[2]=T2h; a.h[3]=T3h; a.h[4]=T4h;
      a.l[0]=Hl;  a.l[1]=T1l; a.l[2]=T2l; a.l[3]=T3l; a.l[4]=T4l;
      k_gemm_mma<true, false><<<gemm_blocks, 256, SMEM_BYTES>>>(
          a, W1th, W1tl, b1, H2, H2h, nullptr); }

    // ---- layer 2 (T0 = H2): 3 SpMVs, then final SpMV fused with head ----
    k_spmv<<<spmv_blocks, 256>>>(H2h, nullptr, T1, T1h, nullptr, 0);
    k_spmv<<<spmv_blocks, 256>>>(T1h, H2,      T2, T2h, nullptr, 1);
    k_spmv<<<spmv_blocks, 256>>>(T2h, T1,      T3, T3h, nullptr, 1);
    k_spmv_out<<<spmv_blocks, 256>>>(T3h, T2, H2, T1, T3, out);
}

// round 11
// speedup vs baseline: 2.8904x; 1.0459x over previous
#include <cuda_runtime.h>
#include <cuda_fp16.h>
#include <cstdint>
#include <math.h>

#define N_NODES 50000
#define N_EDGES 800000
#define FDIM    128
#define SCAN_B  ((N_NODES + 1023) / 1024)
#define AP      40                  // padded halves per smem row (80B)
#define SMEM_BYTES (4 * 2 * 128 * AP * 2)

// ---------------- static device scratch ----------------
__device__ int    g_deg[N_NODES];
__device__ int    g_cnt[N_NODES];
__device__ int    g_ofs[N_NODES];
__device__ int    g_rp[N_NODES + 1];
__device__ float  g_dinv[N_NODES];
__device__ int    g_col[N_EDGES];
__device__ float  g_wt[N_EDGES];
__device__ int    g_bsum[SCAN_B];
__device__ int    g_bofs[SCAN_B];
__device__ __half g_Xh [N_NODES * FDIM];
__device__ __half g_Xl [N_NODES * FDIM];
__device__ __half g_T1h[N_NODES * FDIM];
__device__ __half g_T1l[N_NODES * FDIM];
__device__ __half g_T2h[N_NODES * FDIM];
__device__ __half g_T2l[N_NODES * FDIM];
__device__ __half g_T3h[N_NODES * FDIM];
__device__ __half g_T3l[N_NODES * FDIM];
__device__ __half g_T4h[N_NODES * FDIM];
__device__ __half g_T4l[N_NODES * FDIM];
__device__ __half g_Hh [N_NODES * FDIM];
__device__ __half g_Hl [N_NODES * FDIM];
__device__ __half g_H2h[N_NODES * FDIM];
__device__ __half g_H2l[N_NODES * FDIM];
__device__ __half g_W0th[5 * 128 * 128];   // W transposed [s][n][k], hi
__device__ __half g_W0tl[5 * 128 * 128];   // lo
__device__ __half g_W1th[5 * 128 * 128];
__device__ __half g_W1tl[5 * 128 * 128];
__device__ float  g_C2[5 * FDIM];
__device__ float  g_c0[1];

// ---------------- preprocessing ----------------
__global__ void k_zero() {
    int i = blockIdx.x * blockDim.x + threadIdx.x;
    if (i < N_NODES) { g_deg[i] = 0; g_cnt[i] = 0; }
}

__global__ void k_count(const int* __restrict__ ei) {
    int e = blockIdx.x * blockDim.x + threadIdx.x;
    if (e < N_EDGES) {
        int s = ei[e], d = ei[N_EDGES + e];
        if (s != d) {
            atomicAdd(&g_deg[s], 1);
            atomicAdd(&g_cnt[d], 1);
        }
    }
}

__global__ void k_dinv() {
    int i = blockIdx.x * blockDim.x + threadIdx.x;
    if (i < N_NODES) {
        int dg = g_deg[i];
        g_dinv[i] = (dg > 0) ? rsqrtf((float)dg) : 0.0f;
    }
}

__global__ void k_scanA() {
    __shared__ int wsum[32];
    int tid  = threadIdx.x;
    int lane = tid & 31, wid = tid >> 5;
    int i = blockIdx.x * 1024 + tid;
    int v = (i < N_NODES) ? g_cnt[i] : 0;
    int x = v;
    #pragma unroll
    for (int off = 1; off < 32; off <<= 1) {
        int y = __shfl_up_sync(0xFFFFFFFFu, x, off);
        if (lane >= off) x += y;
    }
    if (lane == 31) wsum[wid] = x;
    __syncthreads();
    if (wid == 0) {
        int y = wsum[lane];
        #pragma unroll
        for (int off = 1; off < 32; off <<= 1) {
            int z = __shfl_up_sync(0xFFFFFFFFu, y, off);
            if (lane >= off) y += z;
        }
        wsum[lane] = y;
    }
    __syncthreads();
    int excl = x - v + (wid > 0 ? wsum[wid - 1] : 0);
    if (i < N_NODES) g_rp[i] = excl;
    if (tid == 0) g_bsum[blockIdx.x] = wsum[31];
}

__global__ void k_scanB() {
    int run = 0;
    for (int b = 0; b < SCAN_B; ++b) {
        g_bofs[b] = run;
        run += g_bsum[b];
    }
    g_rp[N_NODES] = run;
}

__global__ void k_scanC() {
    int i = blockIdx.x * 1024 + threadIdx.x;
    if (i < N_NODES) {
        int r = g_rp[i] + g_bofs[blockIdx.x];
        g_rp[i]  = r;
        g_ofs[i] = r;
    }
}

__global__ void k_fill(const int* __restrict__ ei) {
    int e = blockIdx.x * blockDim.x + threadIdx.x;
    if (e < N_EDGES) {
        int s = ei[e], d = ei[N_EDGES + e];
        if (s != d) {
            int p = atomicAdd(&g_ofs[d], 1);
            g_col[p] = s;
            g_wt[p]  = -g_dinv[s] * g_dinv[d];
        }
    }
}

__global__ void k_fold(const float* __restrict__ W2, const float* __restrict__ b2,
                       const float* __restrict__ Wl, const float* __restrict__ bl) {
    int k = blockIdx.x;
    int f = threadIdx.x;
    const float* row = W2 + ((size_t)k * 128 + f) * 128;
    float s = 0.f;
    #pragma unroll 4
    for (int w = 0; w < 128; ++w) s += row[w] * Wl[w];
    g_C2[k * 128 + f] = s;
    if (k == 0 && f == 0) {
        float c = bl[0];
        for (int w = 0; w < 128; ++w) c += b2[w] * Wl[w];
        g_c0[0] = c;
    }
}

// split W [5][k=128][n=128] fp32 -> transposed [5][n][k] fp16 hi/lo
__global__ void k_wsplit(const float* __restrict__ W,
                         __half* __restrict__ Wh, __half* __restrict__ Wl) {
    int o = blockIdx.x * 256 + threadIdx.x;
    if (o < 5 * 128 * 128) {
        int s = o >> 14, r = o & 16383, n = r >> 7, k = r & 127;
        float w = W[s * 16384 + k * 128 + n];
        __half h = __float2half_rn(w);
        Wh[o] = h;
        Wl[o] = __float2half_rn(w - __half2float(h));
    }
}

// fp32 -> fp16 hi + lo shadows (for x)
__global__ void k_h16(const float* __restrict__ src,
                      __half* __restrict__ dh, __half* __restrict__ dl) {
    int i = blockIdx.x * blockDim.x + threadIdx.x;
    if (i < N_NODES * 32) {
        float4 v = ((const float4*)src)[i];
        __half2 a = __floats2half2_rn(v.x, v.y);
        __half2 b = __floats2half2_rn(v.z, v.w);
        float2 fa = __half22float2(a), fb = __half22float2(b);
        __half2 la = __floats2half2_rn(v.x - fa.x, v.y - fa.y);
        __half2 lb = __floats2half2_rn(v.z - fb.x, v.w - fb.y);
        uint2 u, ul;
        u.x  = *reinterpret_cast<uint32_t*>(&a);
        u.y  = *reinterpret_cast<uint32_t*>(&b);
        ul.x = *reinterpret_cast<uint32_t*>(&la);
        ul.y = *reinterpret_cast<uint32_t*>(&lb);
        ((uint2*)dh)[i] = u;
        ((uint2*)dl)[i] = ul;
    }
}

// ---------------- helpers: hi/lo fp16 pair <-> fp32x4 ----------------
__device__ __forceinline__ float4 load_hl(const __half* __restrict__ h,
                                          const __half* __restrict__ l,
                                          int idx) {
    uint2 uh = ((const uint2*)h)[idx];
    uint2 ul = ((const uint2*)l)[idx];
    float2 h0 = __half22float2(*reinterpret_cast<__half2*>(&uh.x));
    float2 h1 = __half22float2(*reinterpret_cast<__half2*>(&uh.y));
    float2 l0 = __half22float2(*reinterpret_cast<__half2*>(&ul.x));
    float2 l1 = __half22float2(*reinterpret_cast<__half2*>(&ul.y));
    float4 r;
    r.x = h0.x + l0.x; r.y = h0.y + l0.y;
    r.z = h1.x + l1.x; r.w = h1.y + l1.y;
    return r;
}
__device__ __forceinline__ void store_hl(__half* __restrict__ h,
                                         __half* __restrict__ l,
                                         int idx, float4 r) {
    __half2 h0 = __floats2half2_rn(r.x, r.y);
    __half2 h1 = __floats2half2_rn(r.z, r.w);
    float2 f0 = __half22float2(h0), f1 = __half22float2(h1);
    __half2 l0 = __floats2half2_rn(r.x - f0.x, r.y - f0.y);
    __half2 l1 = __floats2half2_rn(r.z - f1.x, r.w - f1.y);
    uint2 hu, lu;
    hu.x = *reinterpret_cast<uint32_t*>(&h0);
    hu.y = *reinterpret_cast<uint32_t*>(&h1);
    lu.x = *reinterpret_cast<uint32_t*>(&l0);
    lu.y = *reinterpret_cast<uint32_t*>(&l1);
    ((uint2*)h)[idx] = hu;
    ((uint2*)l)[idx] = lu;
}

// ---------------- gather core ----------------
__device__ __forceinline__ void gather_row(
    const __half* __restrict__ vinH, int beg, int end, int lane,
    float& ax, float& ay, float& az, float& aw)
{
    int j = beg;
    for (; j + 3 < end; j += 4) {
        int   s0 = g_col[j],     s1 = g_col[j + 1];
        int   s2 = g_col[j + 2], s3 = g_col[j + 3];
        float w0 = g_wt[j],      w1 = g_wt[j + 1];
        float w2 = g_wt[j + 2],  w3 = g_wt[j + 3];
        uint2 u0 = ((const uint2*)(vinH + (size_t)s0 * 128))[lane];
        uint2 u1 = ((const uint2*)(vinH + (size_t)s1 * 128))[lane];
        uint2 u2 = ((const uint2*)(vinH + (size_t)s2 * 128))[lane];
        uint2 u3 = ((const uint2*)(vinH + (size_t)s3 * 128))[lane];
        float2 a0 = __half22float2(*reinterpret_cast<__half2*>(&u0.x));
        float2 b0 = __half22float2(*reinterpret_cast<__half2*>(&u0.y));
        float2 a1 = __half22float2(*reinterpret_cast<__half2*>(&u1.x));
        float2 b1 = __half22float2(*reinterpret_cast<__half2*>(&u1.y));
        float2 a2 = __half22float2(*reinterpret_cast<__half2*>(&u2.x));
        float2 b2 = __half22float2(*reinterpret_cast<__half2*>(&u2.y));
        float2 a3 = __half22float2(*reinterpret_cast<__half2*>(&u3.x));
        float2 b3 = __half22float2(*reinterpret_cast<__half2*>(&u3.y));
        ax += w0 * a0.x + w1 * a1.x + w2 * a2.x + w3 * a3.x;
        ay += w0 * a0.y + w1 * a1.y + w2 * a2.y + w3 * a3.y;
        az += w0 * b0.x + w1 * b1.x + w2 * b2.x + w3 * b3.x;
        aw += w0 * b0.y + w1 * b1.y + w2 * b2.y + w3 * b3.y;
    }
    for (; j < end; ++j) {
        int   s0 = g_col[j];
        float w0 = g_wt[j];
        uint2 u0 = ((const uint2*)(vinH + (size_t)s0 * 128))[lane];
        float2 a0 = __half22float2(*reinterpret_cast<__half2*>(&u0.x));
        float2 b0 = __half22float2(*reinterpret_cast<__half2*>(&u0.y));
        ax += w0 * a0.x; ay += w0 * a0.y; az += w0 * b0.x; aw += w0 * b0.y;
    }
}

// ---------------- SpMV: fp16 gather, fp32 accumulate, hi/lo out ----------
__global__ void k_spmv(const __half* __restrict__ vinH,
                       const __half* __restrict__ prevH,
                       const __half* __restrict__ prevL,
                       __half* __restrict__ voutH,
                       __half* __restrict__ voutL,
                       int cheb) {
    int w    = (blockIdx.x * blockDim.x + threadIdx.x) >> 5;
    int lane = threadIdx.x & 31;
    if (w >= N_NODES) return;
    float ax = 0.f, ay = 0.f, az = 0.f, aw = 0.f;
    gather_row(vinH, g_rp[w], g_rp[w + 1], lane, ax, ay, az, aw);
    float4 r;
    if (cheb) {
        float4 p = load_hl(prevH, prevL, w * 32 + lane);
        r.x = 2.0f * ax - p.x;
        r.y = 2.0f * ay - p.y;
        r.z = 2.0f * az - p.z;
        r.w = 2.0f * aw - p.w;
    } else {
        r.x = ax; r.y = ay; r.z = az; r.w = aw;
    }
    store_hl(voutH, voutL, w * 32 + lane, r);
}

// ---------------- final SpMV fused with head ----------------
__global__ void k_spmv_out(const __half* __restrict__ T3h, const __half* __restrict__ T3l,
                           const __half* __restrict__ T2h, const __half* __restrict__ T2l,
                           const __half* __restrict__ H2h, const __half* __restrict__ H2l,
                           const __half* __restrict__ T1h, const __half* __restrict__ T1l,
                           float* __restrict__ out) {
    __shared__ float c2[5 * 128];
    for (int i = threadIdx.x; i < 5 * 128; i += blockDim.x) c2[i] = g_C2[i];
    __syncthreads();
    int w    = (blockIdx.x * blockDim.x + threadIdx.x) >> 5;
    int lane = threadIdx.x & 31;
    if (w >= N_NODES) return;

    float ax = 0.f, ay = 0.f, az = 0.f, aw = 0.f;
    gather_row(T3h, g_rp[w], g_rp[w + 1], lane, ax, ay, az, aw);

    const int idx = w * 32 + lane;
    float4 p = load_hl(T2h, T2l, idx);
    float4 t4;
    t4.x = 2.0f * ax - p.x;
    t4.y = 2.0f * ay - p.y;
    t4.z = 2.0f * az - p.z;
    t4.w = 2.0f * aw - p.w;

    const int c = lane * 4;
    float s;
    {
        const float* w4 = c2 + 4 * 128 + c;
        s = t4.x * w4[0] + t4.y * w4[1] + t4.z * w4[2] + t4.w * w4[3];
    }
    {
        float4 h = load_hl(H2h, H2l, idx);
        const float* w0 = c2 + 0 * 128 + c;
        s += h.x * w0[0] + h.y * w0[1] + h.z * w0[2] + h.w * w0[3];
    }
    {
        float4 h = load_hl(T1h, T1l, idx);
        const float* w1 = c2 + 1 * 128 + c;
        s += h.x * w1[0] + h.y * w1[1] + h.z * w1[2] + h.w * w1[3];
    }
    {
        const float* w2 = c2 + 2 * 128 + c;
        s += p.x * w2[0] + p.y * w2[1] + p.z * w2[2] + p.w * w2[3];
    }
    {
        float4 h = load_hl(T3h, T3l, idx);
        const float* w3 = c2 + 3 * 128 + c;
        s += h.x * w3[0] + h.y * w3[1] + h.z * w3[2] + h.w * w3[3];
    }
    #pragma unroll
    for (int off = 16; off > 0; off >>= 1) s += __shfl_xor_sync(0xFFFFFFFFu, s, off);
    if (lane == 0) out[w] = s + g_c0[0];
}

// ---------------- tensor-core GEMM: cp.async double-buffered ----------
struct P5 { const __half* h[5]; const __half* l[5]; };

__device__ __forceinline__ void mma16816(float* d, const uint32_t* a, const uint32_t* b) {
    asm volatile(
        "mma.sync.aligned.m16n8k16.row.col.f32.f16.f16.f32 "
        "{%0,%1,%2,%3}, {%4,%5,%6,%7}, {%8,%9}, {%0,%1,%2,%3};"
        : "+f"(d[0]), "+f"(d[1]), "+f"(d[2]), "+f"(d[3])
        : "r"(a[0]), "r"(a[1]), "r"(a[2]), "r"(a[3]), "r"(b[0]), "r"(b[1]));
}

__device__ __forceinline__ void cpa16(uint32_t dst, const void* src, int srcsize) {
    asm volatile("cp.async.cg.shared.global [%0], [%1], 16, %2;"
                 :: "r"(dst), "l"(src), "r"(srcsize));
}

template <bool RELU>
__global__ __launch_bounds__(256, 2)
void k_gemm_mma(P5 A, const __half* __restrict__ Bh, const __half* __restrict__ Bl,
                const float* __restrict__ bias,
                __half* __restrict__ Ch, __half* __restrict__ Cl) {
    extern __shared__ __align__(16) __half sm[];
    const int ARR = 128 * AP;

    const int tid  = threadIdx.x;
    const int wid  = tid >> 5, lane = tid & 31;
    const int g    = lane >> 2, t = lane & 3;
    const int wm   = wid & 3;
    const int wn   = wid >> 2;
    const int m0   = blockIdx.x * 128;

    uint32_t smBase;
    asm("{ .reg .u64 tt; cvta.to.shared.u64 tt, %1; cvt.u32.u64 %0, tt; }"
        : "=r"(smBase) : "l"(sm));

    float acc[2][8][4];
    #pragma unroll
    for (int mt = 0; mt < 2; ++mt)
        #pragma unroll
        for (int nt = 0; nt < 8; ++nt)
            #pragma unroll
            for (int q = 0; q < 4; ++q) acc[mt][nt][q] = 0.f;

    auto do_stage = [&](int c, int buf) {
        const int s = c >> 2, k0 = (c & 3) * 32;
        const __half* Ah = A.h[s];
        const __half* Al = A.l[s];
        const size_t bofs = (size_t)s * 16384 + k0;
        const uint32_t base = smBase + (uint32_t)(buf * 4 * ARR) * 2;
        #pragma unroll
        for (int i = 0; i < 2; ++i) {
            int q = tid + i * 256;
            int row = q >> 2, seg = q & 3;
            int gm = m0 + row;
            int ok  = (gm < N_NODES) ? 16 : 0;
            int gmc = (gm < N_NODES) ? gm : 0;
            uint32_t so = (uint32_t)((row * AP + seg * 8) * 2);
            cpa16(base + 0 * ARR * 2 + so, Ah + (size_t)gmc * 128 + k0 + seg * 8, ok);
            cpa16(base + 1 * ARR * 2 + so, Al + (size_t)gmc * 128 + k0 + seg * 8, ok);
            cpa16(base + 2 * ARR * 2 + so, Bh + bofs + (size_t)row * 128 + seg * 8, 16);
            cpa16(base + 3 * ARR * 2 + so, Bl + bofs + (size_t)row * 128 + seg * 8, 16);
        }
    };

    do_stage(0, 0);
    asm volatile("cp.async.commit_group;" ::: "memory");

    #pragma unroll 1
    for (int c = 0; c < 20; ++c) {
        const int cur = c & 1;
        if (c + 1 < 20) {
            do_stage(c + 1, cur ^ 1);
            asm volatile("cp.async.commit_group;" ::: "memory");
            asm volatile("cp.async.wait_group 1;" ::: "memory");
        } else {
            asm volatile("cp.async.wait_group 0;" ::: "memory");
        }
        __syncthreads();

        const __half* pAh = sm + (cur * 4 + 0) * ARR;
        const __half* pAl = sm + (cur * 4 + 1) * ARR;
        const __half* pBh = sm + (cur * 4 + 2) * ARR;
        const __half* pBl = sm + (cur * 4 + 3) * ARR;

        #pragma unroll
        for (int ks = 0; ks < 2; ++ks) {
            const int kb = ks * 16 + 2 * t;
            uint32_t bf[8][2], ah[2][4], al[2][4];
            #pragma unroll
            for (int nt = 0; nt < 8; ++nt) {
                const int nb = (wn * 64 + nt * 8 + g) * AP + kb;
                bf[nt][0] = *(const uint32_t*)&pBh[nb];
                bf[nt][1] = *(const uint32_t*)&pBh[nb + 8];
            }
            #pragma unroll
            for (int mt = 0; mt < 2; ++mt) {
                const int rb = (wm * 32 + mt * 16 + g) * AP + kb;
                ah[mt][0] = *(const uint32_t*)&pAh[rb];
                ah[mt][1] = *(const uint32_t*)&pAh[rb + 8 * AP];
                ah[mt][2] = *(const uint32_t*)&pAh[rb + 8];
                ah[mt][3] = *(const uint32_t*)&pAh[rb + 8 * AP + 8];
                al[mt][0] = *(const uint32_t*)&pAl[rb];
                al[mt][1] = *(const uint32_t*)&pAl[rb + 8 * AP];
                al[mt][2] = *(const uint32_t*)&pAl[rb + 8];
                al[mt][3] = *(const uint32_t*)&pAl[rb + 8 * AP + 8];
            }
            #pragma unroll
            for (int mt = 0; mt < 2; ++mt)
                #pragma unroll
                for (int nt = 0; nt < 8; ++nt) mma16816(acc[mt][nt], ah[mt], bf[nt]);
            #pragma unroll
            for (int mt = 0; mt < 2; ++mt)
                #pragma unroll
                for (int nt = 0; nt < 8; ++nt) mma16816(acc[mt][nt], al[mt], bf[nt]);
            #pragma unroll
            for (int nt = 0; nt < 8; ++nt) {
                const int nb = (wn * 64 + nt * 8 + g) * AP + kb;
                bf[nt][0] = *(const uint32_t*)&pBl[nb];
                bf[nt][1] = *(const uint32_t*)&pBl[nb + 8];
            }
            #pragma unroll
            for (int mt = 0; mt < 2; ++mt)
                #pragma unroll
                for (int nt = 0; nt < 8; ++nt) mma16816(acc[mt][nt], ah[mt], bf[nt]);
        }
        __syncthreads();
    }

    // ---- epilogue: bias (+relu), hi + lo shadow only ----
    #pragma unroll
    for (int mt = 0; mt < 2; ++mt) {
        #pragma unroll
        for (int half = 0; half < 2; ++half) {
            const int row = m0 + wm * 32 + mt * 16 + g + half * 8;
            if (row < N_NODES) {
                #pragma unroll
                for (int nt = 0; nt < 8; ++nt) {
                    const int col = wn * 64 + nt * 8 + 2 * t;
                    float v0 = acc[mt][nt][half * 2 + 0] + __ldg(bias + col);
                    float v1 = acc[mt][nt][half * 2 + 1] + __ldg(bias + col + 1);
                    if (RELU) { v0 = fmaxf(v0, 0.f); v1 = fmaxf(v1, 0.f); }
                    __half2 h2 = __floats2half2_rn(v0, v1);
                    float2 hf = __half22float2(h2);
                    __half2 l2 = __floats2half2_rn(v0 - hf.x, v1 - hf.y);
                    *(uint32_t*)(Ch + (size_t)row * 128 + col) =
                        *reinterpret_cast<uint32_t*>(&h2);
                    *(uint32_t*)(Cl + (size_t)row * 128 + col) =
                        *reinterpret_cast<uint32_t*>(&l2);
                }
            }
        }
    }
}

// ---------------- launch --------------------------------------------------
extern "C" void kernel_launch(void* const* d_in, const int* in_sizes, int n_in,
                              void* d_out, int out_size) {
    const float* x  = (const float*)d_in[0];
    const int*   ei = (const int*)  d_in[1];
    const float* W0 = (const float*)d_in[2];
    const float* b0 = (const float*)d_in[3];
    const float* W1 = (const float*)d_in[4];
    const float* b1 = (const float*)d_in[5];
    const float* W2 = (const float*)d_in[6];
    const float* b2 = (const float*)d_in[7];
    const float* Wl = (const float*)d_in[8];
    const float* bl = (const float*)d_in[9];
    float* out = (float*)d_out;

    __half *Xh, *Xl, *T1h, *T1l, *T2h, *T2l, *T3h, *T3l, *T4h, *T4l;
    __half *Hh, *Hl, *H2h, *H2l;
    __half *W0th, *W0tl, *W1th, *W1tl;
    cudaGetSymbolAddress((void**)&Xh,   g_Xh);
    cudaGetSymbolAddress((void**)&Xl,   g_Xl);
    cudaGetSymbolAddress((void**)&T1h,  g_T1h);
    cudaGetSymbolAddress((void**)&T1l,  g_T1l);
    cudaGetSymbolAddress((void**)&T2h,  g_T2h);
    cudaGetSymbolAddress((void**)&T2l,  g_T2l);
    cudaGetSymbolAddress((void**)&T3h,  g_T3h);
    cudaGetSymbolAddress((void**)&T3l,  g_T3l);
    cudaGetSymbolAddress((void**)&T4h,  g_T4h);
    cudaGetSymbolAddress((void**)&T4l,  g_T4l);
    cudaGetSymbolAddress((void**)&Hh,   g_Hh);
    cudaGetSymbolAddress((void**)&Hl,   g_Hl);
    cudaGetSymbolAddress((void**)&H2h,  g_H2h);
    cudaGetSymbolAddress((void**)&H2l,  g_H2l);
    cudaGetSymbolAddress((void**)&W0th, g_W0th);
    cudaGetSymbolAddress((void**)&W0tl, g_W0tl);
    cudaGetSymbolAddress((void**)&W1th, g_W1th);
    cudaGetSymbolAddress((void**)&W1tl, g_W1tl);

    cudaFuncSetAttribute(k_gemm_mma<true>,
                         cudaFuncAttributeMaxDynamicSharedMemorySize, SMEM_BYTES);

    const int nb_n = (N_NODES + 255) / 256;
    const int nb_e = (N_EDGES + 255) / 256;
    const int spmv_blocks = (N_NODES * 32 + 255) / 256;
    const int gemm_blocks = (N_NODES + 127) / 128;
    const int conv_blocks = (N_NODES * 32 + 255) / 256;
    const int wsp_blocks  = (5 * 128 * 128 + 255) / 256;

    k_zero  <<<nb_n, 256>>>();
    k_count <<<nb_e, 256>>>(ei);
    k_dinv  <<<nb_n, 256>>>();
    k_scanA <<<SCAN_B, 1024>>>();
    k_scanB <<<1, 1>>>();
    k_scanC <<<SCAN_B, 1024>>>();
    k_fill  <<<nb_e, 256>>>(ei);
    k_fold  <<<5, 128>>>(W2, b2, Wl, bl);
    k_wsplit<<<wsp_blocks, 256>>>(W0, W0th, W0tl);
    k_wsplit<<<wsp_blocks, 256>>>(W1, W1th, W1tl);
    k_h16   <<<conv_blocks, 256>>>(x, Xh, Xl);

    // ---- layer 0 (T0 = x) ----
    k_spmv<<<spmv_blocks, 256>>>(Xh,  nullptr, nullptr, T1h, T1l, 0);
    k_spmv<<<spmv_blocks, 256>>>(T1h, Xh,  Xl,  T2h, T2l, 1);
    k_spmv<<<spmv_blocks, 256>>>(T2h, T1h, T1l, T3h, T3l, 1);
    k_spmv<<<spmv_blocks, 256>>>(T3h, T2h, T2l, T4h, T4l, 1);
    { P5 a;
      a.h[0]=Xh;  a.h[1]=T1h; a.h[2]=T2h; a.h[3]=T3h; a.h[4]=T4h;
      a.l[0]=Xl;  a.l[1]=T1l; a.l[2]=T2l; a.l[3]=T3l; a.l[4]=T4l;
      k_gemm_mma<true><<<gemm_blocks, 256, SMEM_BYTES>>>(
          a, W0th, W0tl, b0, Hh, Hl); }

    // ---- layer 1 (T0 = H) ----
    k_spmv<<<spmv_blocks, 256>>>(Hh,  nullptr, nullptr, T1h, T1l, 0);
    k_spmv<<<spmv_blocks, 256>>>(T1h, Hh,  Hl,  T2h, T2l, 1);
    k_spmv<<<spmv_blocks, 256>>>(T2h, T1h, T1l, T3h, T3l, 1);
    k_spmv<<<spmv_blocks, 256>>>(T3h, T2h, T2l, T4h, T4l, 1);
    { P5 a;
      a.h[0]=Hh;  a.h[1]=T1h; a.h[2]=T2h; a.h[3]=T3h; a.h[4]=T4h;
      a.l[0]=Hl;  a.l[1]=T1l; a.l[2]=T2l; a.l[3]=T3l; a.l[4]=T4l;
      k_gemm_mma<true><<<gemm_blocks, 256, SMEM_BYTES>>>(
          a, W1th, W1tl, b1, H2h, H2l); }

    // ---- layer 2 (T0 = H2): 3 SpMVs, then final SpMV fused with head ----
    k_spmv<<<spmv_blocks, 256>>>(H2h, nullptr, nullptr, T1h, T1l, 0);
    k_spmv<<<spmv_blocks, 256>>>(T1h, H2h, H2l, T2h, T2l, 1);
    k_spmv<<<spmv_blocks, 256>>>(T2h, T1h, T1l, T3h, T3l, 1);
    k_spmv_out<<<spmv_blocks, 256>>>(T3h, T3l, T2h, T2l, H2h, H2l, T1h, T1l, out);
}